// round 12
// baseline (speedup 1.0000x reference)
#include <cuda_runtime.h>
#include <math.h>

#define Bsz 8
#define Cc 64
#define HWd 128
#define NPIX (HWd*HWd)
#define PLANE ((size_t)Cc*NPIX)
#define BS ((size_t)Bsz*Cc*NPIX)
#define LEAKv 0.2f
#define CLAMPv 0.8f
#define EPSv 1e-5f
#define CWS (64*64*9)

#define CTW 16
#define CTH 8
#define INC 18
#define INREAL 180
#define INPAD 196             // uint2 stride, 196 % 16 == 4
#define WPAD 68               // 68 % 16 == 4
#define SW_CH (36*WPAD)       // uint2 per weight smem buffer
#define WSET 18432            // uint2 per packed weight set
#define IN_CH (4*INPAD)       // uint2 per input buffer
#define SMEM_CONV ((2*SW_CH + 2*IN_CH) * 8)   // 51712 bytes

// ---------------- scratch ----------------
__device__ float g_x1[Bsz*Cc*NPIX];
__device__ float g_x2[Bsz*Cc*NPIX];
__device__ float g_y1[Bsz*Cc*NPIX];
__device__ float g_y2[Bsz*Cc*NPIX];
__device__ float g_rb[Bsz*Cc*NPIX];
__device__ float g_sb[Bsz*Cc*NPIX];
__device__ float g_xf[Bsz*Cc*NPIX];
__device__ float g_hb[Bsz*Cc*NPIX];
__device__ float g_gv[Bsz*Cc];
__device__ int   g_sel[Bsz*2];
__device__ float g_cofsel[Bsz*2];
__device__ uint2 g_wpack[14*WSET];

__device__ __forceinline__ unsigned f2tf32(float f) {
    unsigned r;
    asm("cvt.rna.tf32.f32 %0, %1;" : "=r"(r) : "f"(f));
    return r;
}

__device__ __forceinline__ void mma_tf32(float* d, const unsigned* a, const unsigned* b) {
    asm volatile(
        "mma.sync.aligned.m16n8k8.row.col.f32.tf32.tf32.f32 "
        "{%0,%1,%2,%3}, {%4,%5,%6,%7}, {%8,%9}, {%0,%1,%2,%3};"
        : "+f"(d[0]), "+f"(d[1]), "+f"(d[2]), "+f"(d[3])
        : "r"(a[0]), "r"(a[1]), "r"(a[2]), "r"(a[3]), "r"(b[0]), "r"(b[1]));
}

__device__ __forceinline__ void cp_async8(unsigned sdst, const void* gsrc) {
    asm volatile("cp.async.ca.shared.global [%0], [%1], 8;" :: "r"(sdst), "l"(gsrc));
}
__device__ __forceinline__ void cp_commit() { asm volatile("cp.async.commit_group;" ::: "memory"); }
__device__ __forceinline__ void cp_wait0()  { asm volatile("cp.async.wait_group 0;" ::: "memory"); }

// ---------------- single merged weight repack ----------------
__global__ void pack_all(const float* __restrict__ w1, const float* __restrict__ w2,
                         const float* __restrict__ e1, const float* __restrict__ e2,
                         uint2* __restrict__ dst)
{
    int i = blockIdx.x*blockDim.x + threadIdx.x;
    if (i >= 14*WSET) return;
    int s = i / WSET;
    int r = i % WSET;
    const float* src;
    if (s < 3)       src = w1 + (size_t)s * CWS;
    else if (s < 6)  src = w2 + (size_t)(s-3) * CWS;
    else if (s < 10) src = e1 + (size_t)(s-6) * CWS;
    else             src = e2 + (size_t)(s-10) * CWS;
    int ck  = r / 2304;
    int rem = r % 2304;
    int q = rem >> 6, oc = rem & 63;
    int kq = q & 3, tap = q >> 2;
    int ic = ck*8 + kq;
    dst[i] = make_uint2(f2tf32(src[(oc*64 + ic)*9 + tap]),
                        f2tf32(src[(oc*64 + ic + 4)*9 + tap]));
}

// ---------------- 3x3 conv: TF32 MMA, double-buffered, wait+sync AFTER MMA ----------------
template<int MODE>
__global__ __launch_bounds__(256)
void conv3x3_mma(const float* __restrict__ in, const uint2* __restrict__ wpk,
                 const float* __restrict__ bias, float* __restrict__ out,
                 const float* __restrict__ add1, const float* __restrict__ add2,
                 const float* __restrict__ spre,
                 const int* __restrict__ sel, const float* __restrict__ cofsel,
                 int slot, int accum)
{
    extern __shared__ uint2 dsm[];
    uint2* s_w  = dsm;               // 2 * SW_CH
    uint2* s_in = dsm + 2*SW_CH;     // 2 * IN_CH

    int tid = threadIdx.x;
    int wid = tid >> 5;
    int lane = tid & 31;
    int l4 = lane & 3;
    int g  = lane >> 2;
    int warp_m = wid & 3;
    int warp_n = wid >> 2;
    int wm2 = warp_m * 2;
    int n0 = warp_n * 32;

    int b  = blockIdx.z;
    int w0 = blockIdx.x * CTW;
    int h0 = blockIdx.y * CTH;

    const uint2* wp = wpk;
    const float* bbase = bias;
    float cw = 1.f;
    if (MODE == 4 || MODE == 5) {
        int e = sel[b*2 + slot];
        wp = wpk + e * WSET;
        bbase = bias + e * Cc;
        if (MODE == 5) cw = cofsel[b*2 + slot];
    }
    const float* inb = in + (size_t)b * PLANE;

    unsigned wdst8[9];
    unsigned wsrc[9];
    unsigned swbase = (unsigned)__cvta_generic_to_shared(s_w);
    #pragma unroll
    for (int t = 0; t < 9; t++) {
        int i = tid + t*256;
        int q = i >> 6, oc = i & 63;
        wdst8[t] = (unsigned)((q*WPAD + oc) * 8);
        wsrc[t] = (unsigned)(q*64 + oc);
    }

    bool iact[3], ival[3];
    unsigned ioff[3];
    int ismem[3];
    #pragma unroll
    for (int t = 0; t < 3; t++) {
        int i = tid + t*256;
        iact[t] = (i < 4*INREAL);
        int kq  = i / INREAL;
        int rem = i - kq*INREAL;
        int rr = rem / INC;
        int cc = rem - rr*INC;
        int h = h0 - 1 + rr;
        int w = w0 - 1 + cc;
        ival[t] = iact[t] && ((unsigned)h < HWd) && ((unsigned)w < HWd);
        ismem[t] = kq*INPAD + rem;
        ioff[t] = ival[t] ? (unsigned)(kq*NPIX + h*HWd + w) : 0u;
    }

    float d[2][4][4];
    #pragma unroll
    for (int mt = 0; mt < 2; mt++)
        #pragma unroll
        for (int nt = 0; nt < 4; nt++)
            #pragma unroll
            for (int r = 0; r < 4; r++) d[mt][nt][r] = 0.f;

    // ---- prologue: fill stage 0, prefetch LDG for stage 1 ----
    #pragma unroll
    for (int t = 0; t < 9; t++)
        cp_async8(swbase + wdst8[t], wp + wsrc[t]);
    cp_commit();                                  // w0

    float ipf0[3], ipf1[3];
    #pragma unroll
    for (int t = 0; t < 3; t++) {                 // input ck0
        ipf0[t] = ival[t] ? inb[ioff[t]] : 0.f;
        ipf1[t] = ival[t] ? inb[ioff[t] + 4*NPIX] : 0.f;
    }
    #pragma unroll
    for (int t = 0; t < 3; t++)                   // STS ck0 -> ibuf0
        if (iact[t]) s_in[ismem[t]] = make_uint2(f2tf32(ipf0[t]), f2tf32(ipf1[t]));
    #pragma unroll
    for (int t = 0; t < 3; t++) {                 // LDG ck1 -> regs
        if (ival[t]) {
            ipf0[t] = inb[ioff[t] + 8*NPIX];
            ipf1[t] = inb[ioff[t] + 12*NPIX];
        }
    }
    cp_wait0();                                   // own w0 done
    __syncthreads();                              // everyone's w0 + ibuf0 visible

    #pragma unroll 1
    for (int ck = 0; ck < 8; ck++) {
        if (ck < 7) {
            // STS input ck+1 into other buffer (prev MMA on that buffer fenced by last sync)
            int ibo = ((ck+1)&1) * IN_CH;
            #pragma unroll
            for (int t = 0; t < 3; t++)
                if (iact[t]) s_in[ibo + ismem[t]] = make_uint2(f2tf32(ipf0[t]), f2tf32(ipf1[t]));
            // cp weights ck+1 into other buffer
            unsigned bufoff = (unsigned)(((ck+1)&1) * SW_CH * 8);
            const uint2* src = wp + (ck+1)*2304;
            #pragma unroll
            for (int t = 0; t < 9; t++)
                cp_async8(swbase + bufoff + wdst8[t], src + wsrc[t]);
            cp_commit();
            // LDG input ck+2 -> regs
            if (ck < 6) {
                unsigned ib = (unsigned)((ck+2) * 8*NPIX);
                #pragma unroll
                for (int t = 0; t < 3; t++) {
                    if (ival[t]) {
                        ipf0[t] = inb[ioff[t] + ib];
                        ipf1[t] = inb[ioff[t] + ib + 4*NPIX];
                    }
                }
            }
        }

        // MMA on stage ck (fills overlap with this)
        const uint2* si  = s_in + (ck&1)*IN_CH;
        const uint2* swc = s_w  + (ck&1)*SW_CH;
        #pragma unroll
        for (int tap = 0; tap < 9; tap++) {
            int ky = tap / 3, kx = tap % 3;
            int abase = l4*INPAD + (wm2 + ky)*INC + kx + g;
            unsigned a[2][4];
            #pragma unroll
            for (int mt = 0; mt < 2; mt++) {
                uint2 p0 = si[abase + mt*INC];
                uint2 p1 = si[abase + mt*INC + 8];
                a[mt][0] = p0.x; a[mt][1] = p1.x; a[mt][2] = p0.y; a[mt][3] = p1.y;
            }
            int bb = (tap*4 + l4)*WPAD + n0 + g;
            unsigned bq[4][2];
            #pragma unroll
            for (int nt = 0; nt < 4; nt++) {
                uint2 q = swc[bb + nt*8];
                bq[nt][0] = q.x; bq[nt][1] = q.y;
            }
            #pragma unroll
            for (int mt = 0; mt < 2; mt++)
                #pragma unroll
                for (int nt = 0; nt < 4; nt++)
                    mma_tf32(d[mt][nt], a[mt], bq[nt]);
        }

        if (ck < 7) {
            cp_wait0();        // own w_{ck+1} done (long since; overlapped with MMA)
            __syncthreads();   // everyone's w_{ck+1} + ibuf_{ck+1} visible; ck buffers free
        }
    }

    // epilogue
    #pragma unroll
    for (int mt = 0; mt < 2; mt++) {
        int h = h0 + wm2 + mt;
        #pragma unroll
        for (int nt = 0; nt < 4; nt++) {
            int oc = n0 + nt*8 + l4*2;
            float bv0 = bbase[oc], bv1 = bbase[oc+1];
            size_t p0 = (size_t)b*PLANE + (size_t)oc*NPIX + (size_t)h*HWd;
            size_t p1 = p0 + NPIX;
            int wa = w0 + g, wb2 = wa + 8;
            float vv[4] = { d[mt][nt][0] + bv0, d[mt][nt][1] + bv1,
                            d[mt][nt][2] + bv0, d[mt][nt][3] + bv1 };
            size_t ix[4] = { p0 + wa, p1 + wa, p0 + wb2, p1 + wb2 };
            #pragma unroll
            for (int r = 0; r < 4; r++) {
                size_t idx = ix[r];
                float v = vv[r];
                if (MODE == 1) {
                    v += add1[idx] + add2[idx];
                } else if (MODE == 2) {
                    v += add1[idx];
                } else if (MODE == 3) {
                    float sp = spre[idx];
                    float sig = 1.f / (1.f + expf(-sp));
                    float s = CLAMPv * (2.f*sig - 1.f);
                    v += add1[idx] + add2[idx] * expf(s);
                } else if (MODE == 4) {
                    v = v > 0.f ? v : LEAKv * v;
                } else if (MODE == 5) {
                    v = (v + add1[idx]) * cw;
                    if (accum) v += out[idx];
                }
                out[idx] = v;
            }
        }
    }
}

// ---------------- 1x1 GEMM via TF32 MMA ----------------
#define GPAD 132

template<int IC>
__global__ __launch_bounds__(256)
void gemm1x1_mma(const float* __restrict__ inA, const float* __restrict__ inB,
                 const float* __restrict__ W, const float* __restrict__ bias,
                 float* __restrict__ outA, float* __restrict__ outB)
{
    __shared__ uint2 s_x[8 * GPAD];
    __shared__ uint2 s_w[8 * WPAD];

    int tid = threadIdx.x;
    int wid = tid >> 5;
    int lane = tid & 31;
    int l4 = lane & 3;
    int g  = lane >> 2;
    int warp_m = wid & 3;
    int warp_n = wid >> 2;
    int n0 = warp_n * 32;

    int b   = blockIdx.z;
    int oc0 = blockIdx.y * 64;
    int p0  = blockIdx.x * 128;

    float d[2][4][4];
    #pragma unroll
    for (int mt = 0; mt < 2; mt++)
        #pragma unroll
        for (int nt = 0; nt < 4; nt++)
            #pragma unroll
            for (int r = 0; r < 4; r++) d[mt][nt][r] = 0.f;

    for (int ch = 0; ch < IC; ch += 16) {
        for (int i = tid; i < 8*128; i += 256) {
            int q = i >> 7;
            int p = i & 127;
            int ic0 = ch + (q >> 2)*8 + (q & 3);
            unsigned v0, v1;
            if (inB != nullptr) {
                const float* s0 = (ic0 < 64) ? inA : inB;
                const float* s1 = (ic0+4 < 64) ? inA : inB;
                v0 = f2tf32(s0[(size_t)b*PLANE + (size_t)(ic0 & 63)*NPIX + p0 + p]);
                v1 = f2tf32(s1[(size_t)b*PLANE + (size_t)((ic0+4) & 63)*NPIX + p0 + p]);
            } else {
                v0 = f2tf32(inA[((size_t)b*IC + ic0)*NPIX + p0 + p]);
                v1 = f2tf32(inA[((size_t)b*IC + ic0 + 4)*NPIX + p0 + p]);
            }
            s_x[q*GPAD + p] = make_uint2(v0, v1);
        }
        for (int i = tid; i < 8*64; i += 256) {
            int q  = i & 7;
            int oc = i >> 3;
            int ic0 = ch + (q >> 2)*8 + (q & 3);
            size_t o = (size_t)(oc0 + oc)*IC + ic0;
            s_w[q*WPAD + oc] = make_uint2(f2tf32(W[o]), f2tf32(W[o + 4]));
        }
        __syncthreads();

        #pragma unroll
        for (int ks = 0; ks < 2; ks++) {
            int abase = (ks*4 + l4)*GPAD + warp_m*32 + g;
            unsigned a[2][4];
            #pragma unroll
            for (int mt = 0; mt < 2; mt++) {
                uint2 q0 = s_x[abase + mt*16];
                uint2 q1 = s_x[abase + mt*16 + 8];
                a[mt][0] = q0.x; a[mt][1] = q1.x; a[mt][2] = q0.y; a[mt][3] = q1.y;
            }
            int bb = (ks*4 + l4)*WPAD + n0 + g;
            unsigned bq[4][2];
            #pragma unroll
            for (int nt = 0; nt < 4; nt++) {
                uint2 q = s_w[bb + nt*8];
                bq[nt][0] = q.x; bq[nt][1] = q.y;
            }
            #pragma unroll
            for (int mt = 0; mt < 2; mt++)
                #pragma unroll
                for (int nt = 0; nt < 4; nt++)
                    mma_tf32(d[mt][nt], a[mt], bq[nt]);
        }
        __syncthreads();
    }

    #pragma unroll
    for (int mt = 0; mt < 2; mt++) {
        #pragma unroll
        for (int nt = 0; nt < 4; nt++) {
            int oc = oc0 + n0 + nt*8 + l4*2;
            float bv0 = bias ? bias[oc] : 0.f;
            float bv1 = bias ? bias[oc+1] : 0.f;
            float* dst = outA;
            int ocd = oc;
            if (outB != nullptr && oc >= 64) { dst = outB; ocd = oc - 64; }
            int pix = p0 + warp_m*32 + mt*16 + g;
            size_t q0 = (size_t)b*PLANE + (size_t)ocd*NPIX + pix;
            size_t q1 = q0 + NPIX;
            dst[q0]     = d[mt][nt][0] + bv0;
            dst[q1]     = d[mt][nt][1] + bv1;
            dst[q0 + 8] = d[mt][nt][2] + bv0;
            dst[q1 + 8] = d[mt][nt][3] + bv1;
        }
    }
}

// ---------------- instance norm (in-place) ----------------
__global__ __launch_bounds__(256)
void inorm_k(float* __restrict__ r, const float* __restrict__ nw, const float* __restrict__ nb)
{
    int bidx = blockIdx.x;
    int b = bidx >> 5, c = bidx & 31;
    float* p = r + (size_t)b*PLANE + (size_t)c*NPIX;
    int tid = threadIdx.x;
    float s = 0.f, s2 = 0.f;
    for (int i = tid; i < NPIX; i += 256) { float v = p[i]; s += v; s2 += v*v; }
    __shared__ float sh[256], sh2[256];
    sh[tid] = s; sh2[tid] = s2;
    __syncthreads();
    for (int st = 128; st; st >>= 1) {
        if (tid < st) { sh[tid] += sh[tid+st]; sh2[tid] += sh2[tid+st]; }
        __syncthreads();
    }
    float mean = sh[0] * (1.f/NPIX);
    float var = sh2[0] * (1.f/NPIX) - mean*mean;
    float inv = rsqrtf(var + EPSv);
    float ga = nw[c], be = nb[c];
    for (int i = tid; i < NPIX; i += 256)
        p[i] = (p[i] - mean) * inv * ga + be;
}

// ---------------- pool ----------------
__global__ __launch_bounds__(256)
void pool_k(const float* __restrict__ xf, float* __restrict__ g)
{
    int bc = blockIdx.x;
    const float* p = xf + (size_t)bc * NPIX;
    int tid = threadIdx.x;
    float mx = -1e30f, sm = 0.f;
    for (int i = tid; i < NPIX; i += 256) { float v = p[i]; mx = fmaxf(mx, v); sm += v; }
    __shared__ float smx[256], ssm[256];
    smx[tid] = mx; ssm[tid] = sm;
    __syncthreads();
    for (int st = 128; st; st >>= 1) {
        if (tid < st) { smx[tid] = fmaxf(smx[tid], smx[tid+st]); ssm[tid] += ssm[tid+st]; }
        __syncthreads();
    }
    if (tid == 0) g[bc] = smx[0] + ssm[0] * (1.f/NPIX);
}

// ---------------- gating ----------------
__global__ void gate_k(const float* __restrict__ g,
                       const float* __restrict__ gw0, const float* __restrict__ gb0,
                       const float* __restrict__ gw1, const float* __restrict__ gb1,
                       float* __restrict__ cof_out, int* __restrict__ sel,
                       float* __restrict__ cofsel)
{
    int b = threadIdx.x;
    if (b >= Bsz) return;
    float lg[4], noi[4];
    for (int e = 0; e < 4; e++) {
        float a0 = gb0[e], a1 = gb1[e];
        for (int c = 0; c < 64; c++) {
            float gv = g[b*64 + c];
            a0 += gw0[e*64 + c] * gv;
            a1 += gw1[e*64 + c] * gv;
        }
        lg[e] = a1 > 0.f ? a1 : LEAKv * a1;
        noi[e] = fmaxf(a0, 0.f) + log1pf(expf(-fabsf(a0)));
    }
    float m = 0.25f * (noi[0] + noi[1] + noi[2] + noi[3]);
    float var = 0.f;
    for (int e = 0; e < 4; e++) { float dd = noi[e] - m; var += dd*dd; }
    float sd = sqrtf(var / 3.f);
    float sc[4];
    for (int e = 0; e < 4; e++) sc[e] = lg[e] + (noi[e] - m) / sd;
    int i0 = 0;
    for (int e = 1; e < 4; e++) if (sc[e] > sc[i0]) i0 = e;
    int i1 = -1;
    for (int e = 0; e < 4; e++) {
        if (e == i0) continue;
        if (i1 < 0 || sc[e] > sc[i1]) i1 = e;
    }
    float mm = fmaxf(lg[i0], lg[i1]);
    float e0 = expf(lg[i0] - mm), e1 = expf(lg[i1] - mm);
    float c0 = e0 / (e0 + e1), c1 = e1 / (e0 + e1);
    if (cof_out) {
        for (int e = 0; e < 4; e++) cof_out[b*4 + e] = 0.f;
        cof_out[b*4 + i0] = c0;
        cof_out[b*4 + i1] = c1;
    }
    sel[b*2 + 0] = i0; sel[b*2 + 1] = i1;
    cofsel[b*2 + 0] = c0; cofsel[b*2 + 1] = c1;
}

// ---------------- launch ----------------
extern "C" void kernel_launch(void* const* d_in, const int* in_sizes, int n_in,
                              void* d_out, int out_size)
{
    const float* x       = (const float*)d_in[0];
    const float* winv    = (const float*)d_in[1];
    const float* blk_w1  = (const float*)d_in[2];
    const float* blk_b1  = (const float*)d_in[3];
    const float* blk_nw  = (const float*)d_in[4];
    const float* blk_nb  = (const float*)d_in[5];
    const float* blk_w2  = (const float*)d_in[6];
    const float* blk_b2  = (const float*)d_in[7];
    const float* fuse_w  = (const float*)d_in[8];
    const float* fuse_b  = (const float*)d_in[9];
    const float* gw0     = (const float*)d_in[10];
    const float* gb0     = (const float*)d_in[11];
    const float* gw1     = (const float*)d_in[12];
    const float* gb1     = (const float*)d_in[13];
    const float* ew1     = (const float*)d_in[14];
    const float* eb1     = (const float*)d_in[15];
    const float* ew2     = (const float*)d_in[16];
    const float* eb2     = (const float*)d_in[17];
    float* out = (float*)d_out;
    float* cof_out = ((size_t)out_size >= BS + Bsz*4) ? out + BS : nullptr;

    float *x1, *x2, *y1, *y2, *rb, *sb, *xf, *hb, *gv, *cofsel; int* sel; uint2* wpack;
    void* p;
    cudaGetSymbolAddress(&p, g_x1);  x1 = (float*)p;
    cudaGetSymbolAddress(&p, g_x2);  x2 = (float*)p;
    cudaGetSymbolAddress(&p, g_y1);  y1 = (float*)p;
    cudaGetSymbolAddress(&p, g_y2);  y2 = (float*)p;
    cudaGetSymbolAddress(&p, g_rb);  rb = (float*)p;
    cudaGetSymbolAddress(&p, g_sb);  sb = (float*)p;
    cudaGetSymbolAddress(&p, g_xf);  xf = (float*)p;
    cudaGetSymbolAddress(&p, g_hb);  hb = (float*)p;
    cudaGetSymbolAddress(&p, g_gv);  gv = (float*)p;
    cudaGetSymbolAddress(&p, g_sel); sel = (int*)p;
    cudaGetSymbolAddress(&p, g_cofsel); cofsel = (float*)p;
    cudaGetSymbolAddress(&p, g_wpack);  wpack = (uint2*)p;

    cudaFuncSetAttribute(conv3x3_mma<0>, cudaFuncAttributeMaxDynamicSharedMemorySize, SMEM_CONV);
    cudaFuncSetAttribute(conv3x3_mma<1>, cudaFuncAttributeMaxDynamicSharedMemorySize, SMEM_CONV);
    cudaFuncSetAttribute(conv3x3_mma<2>, cudaFuncAttributeMaxDynamicSharedMemorySize, SMEM_CONV);
    cudaFuncSetAttribute(conv3x3_mma<3>, cudaFuncAttributeMaxDynamicSharedMemorySize, SMEM_CONV);
    cudaFuncSetAttribute(conv3x3_mma<4>, cudaFuncAttributeMaxDynamicSharedMemorySize, SMEM_CONV);
    cudaFuncSetAttribute(conv3x3_mma<5>, cudaFuncAttributeMaxDynamicSharedMemorySize, SMEM_CONV);

    dim3 cgrid(HWd/CTW, HWd/CTH, Bsz);
    dim3 wgrid(NPIX/128, 2, Bsz);
    dim3 fgrid(NPIX/128, 1, Bsz);

    pack_all<<<(14*WSET+255)/256, 256>>>(blk_w1, blk_w2, ew1, ew2, wpack);

    gemm1x1_mma<128><<<wgrid, 256>>>(x, nullptr, winv, nullptr, x1, x2);

    conv3x3_mma<0><<<cgrid, 256, SMEM_CONV>>>(x2, wpack + 0*WSET, blk_b1 + 0*64, rb,
                                   nullptr, nullptr, nullptr, nullptr, nullptr, 0, 0);
    inorm_k<<<Bsz*32, 256>>>(rb, blk_nw + 0*32, blk_nb + 0*32);
    conv3x3_mma<1><<<cgrid, 256, SMEM_CONV>>>(rb, wpack + 3*WSET, blk_b2 + 0*64, y1,
                                   x2, x1, nullptr, nullptr, nullptr, 0, 0);

    conv3x3_mma<0><<<cgrid, 256, SMEM_CONV>>>(y1, wpack + 2*WSET, blk_b1 + 2*64, rb,
                                   nullptr, nullptr, nullptr, nullptr, nullptr, 0, 0);
    inorm_k<<<Bsz*32, 256>>>(rb, blk_nw + 2*32, blk_nb + 2*32);
    conv3x3_mma<2><<<cgrid, 256, SMEM_CONV>>>(rb, wpack + 5*WSET, blk_b2 + 2*64, sb,
                                   y1, nullptr, nullptr, nullptr, nullptr, 0, 0);

    conv3x3_mma<0><<<cgrid, 256, SMEM_CONV>>>(y1, wpack + 1*WSET, blk_b1 + 1*64, rb,
                                   nullptr, nullptr, nullptr, nullptr, nullptr, 0, 0);
    inorm_k<<<Bsz*32, 256>>>(rb, blk_nw + 1*32, blk_nb + 1*32);
    conv3x3_mma<3><<<cgrid, 256, SMEM_CONV>>>(rb, wpack + 4*WSET, blk_b2 + 1*64, y2,
                                   y1, x2, sb, nullptr, nullptr, 0, 0);

    gemm1x1_mma<128><<<fgrid, 256>>>(y1, y2, fuse_w, fuse_b, xf, nullptr);

    pool_k<<<Bsz*64, 256>>>(xf, gv);
    gate_k<<<1, 32>>>(gv, gw0, gb0, gw1, gb1, cof_out, sel, cofsel);

    for (int slot = 0; slot < 2; slot++) {
        conv3x3_mma<4><<<cgrid, 256, SMEM_CONV>>>(xf, wpack + 6*WSET, eb1, hb,
                                       nullptr, nullptr, nullptr, sel, cofsel, slot, 0);
        conv3x3_mma<5><<<cgrid, 256, SMEM_CONV>>>(hb, wpack + 10*WSET, eb2, out,
                                       xf, nullptr, nullptr, sel, cofsel, slot, slot);
    }
}

// round 13
// speedup vs baseline: 1.1804x; 1.1804x over previous
#include <cuda_runtime.h>
#include <math.h>

#define Bsz 8
#define Cc 64
#define HWd 128
#define NPIX (HWd*HWd)
#define PLANE ((size_t)Cc*NPIX)
#define BS ((size_t)Bsz*Cc*NPIX)
#define LEAKv 0.2f
#define CLAMPv 0.8f
#define EPSv 1e-5f
#define CWS (64*64*9)

#define CTW 16
#define CTH 8
#define INC 18
#define INREAL 180
#define INPAD 196             // uint2 stride, 196 % 16 == 4
#define WPAD 68               // 68 % 16 == 4
#define SW_CH (36*WPAD)       // uint2 per weight smem buffer
#define WSET 18432            // uint2 per packed weight set

// ---------------- scratch ----------------
__device__ float g_x1[Bsz*Cc*NPIX];
__device__ float g_x2[Bsz*Cc*NPIX];
__device__ float g_y1[Bsz*Cc*NPIX];
__device__ float g_y2[Bsz*Cc*NPIX];
__device__ float g_rb[Bsz*Cc*NPIX];
__device__ float g_sb[Bsz*Cc*NPIX];
__device__ float g_xf[Bsz*Cc*NPIX];
__device__ float g_hb[Bsz*Cc*NPIX];
__device__ float g_gv[Bsz*Cc];
__device__ int   g_sel[Bsz*2];
__device__ float g_cofsel[Bsz*2];
__device__ uint2 g_wpack[14*WSET];

__device__ __forceinline__ unsigned f2tf32(float f) {
    unsigned r;
    asm("cvt.rna.tf32.f32 %0, %1;" : "=r"(r) : "f"(f));
    return r;
}

__device__ __forceinline__ void mma_tf32(float* d, const unsigned* a, const unsigned* b) {
    asm volatile(
        "mma.sync.aligned.m16n8k8.row.col.f32.tf32.tf32.f32 "
        "{%0,%1,%2,%3}, {%4,%5,%6,%7}, {%8,%9}, {%0,%1,%2,%3};"
        : "+f"(d[0]), "+f"(d[1]), "+f"(d[2]), "+f"(d[3])
        : "r"(a[0]), "r"(a[1]), "r"(a[2]), "r"(a[3]), "r"(b[0]), "r"(b[1]));
}

__device__ __forceinline__ void cp_async8(unsigned sdst, const void* gsrc) {
    asm volatile("cp.async.ca.shared.global [%0], [%1], 8;" :: "r"(sdst), "l"(gsrc));
}
__device__ __forceinline__ void cp_commit() { asm volatile("cp.async.commit_group;" ::: "memory"); }
__device__ __forceinline__ void cp_wait1()  { asm volatile("cp.async.wait_group 1;" ::: "memory"); }
__device__ __forceinline__ void cp_wait0()  { asm volatile("cp.async.wait_group 0;" ::: "memory"); }

// ---------------- single merged weight repack ----------------
__global__ void pack_all(const float* __restrict__ w1, const float* __restrict__ w2,
                         const float* __restrict__ e1, const float* __restrict__ e2,
                         uint2* __restrict__ dst)
{
    int i = blockIdx.x*blockDim.x + threadIdx.x;
    if (i >= 14*WSET) return;
    int s = i / WSET;
    int r = i % WSET;
    const float* src;
    if (s < 3)       src = w1 + (size_t)s * CWS;
    else if (s < 6)  src = w2 + (size_t)(s-3) * CWS;
    else if (s < 10) src = e1 + (size_t)(s-6) * CWS;
    else             src = e2 + (size_t)(s-10) * CWS;
    int ck  = r / 2304;
    int rem = r % 2304;
    int q = rem >> 6, oc = rem & 63;
    int kq = q & 3, tap = q >> 2;
    int ic = ck*8 + kq;
    dst[i] = make_uint2(f2tf32(src[(oc*64 + ic)*9 + tap]),
                        f2tf32(src[(oc*64 + ic + 4)*9 + tap]));
}

// ---------------- 3x3 conv: TF32 MMA + cp.async packed weights (R10 core) ----------------
// MODE 0: out = conv+bias
// MODE 1: out = conv+bias+add1+add2
// MODE 2: out = conv+bias+add1
// MODE 3: out = conv+bias+add1 + add2*exp(clamp*(2sig(spre)-1))
// MODE 4: MERGED expert conv1: z=(slot*8+b); dst[slot] = cof*lrelu(conv+b_e)
// MODE 5: MERGED expert conv2: K=128 over (in: chunks 0-7, add2: chunks 8-15),
//         weights e0/e1 per half; out = acc + c0*b0 + c1*b1 + (c0+c1)*add1
template<int MODE>
__global__ __launch_bounds__(256)
void conv3x3_mma(const float* __restrict__ in, const uint2* __restrict__ wpk,
                 const float* __restrict__ bias, float* __restrict__ out,
                 const float* __restrict__ add1, const float* __restrict__ add2,
                 const float* __restrict__ spre,
                 const int* __restrict__ sel, const float* __restrict__ cofsel,
                 float* __restrict__ out2)
{
    __shared__ uint2 s_in[4 * INPAD];
    __shared__ uint2 s_w[2 * SW_CH];

    const int NCK = (MODE == 5) ? 16 : 8;

    int tid = threadIdx.x;
    int wid = tid >> 5;
    int lane = tid & 31;
    int l4 = lane & 3;
    int g  = lane >> 2;
    int warp_m = wid & 3;
    int warp_n = wid >> 2;
    int wm2 = warp_m * 2;
    int n0 = warp_n * 32;

    int bz = blockIdx.z;
    int b    = (MODE == 4) ? (bz & 7) : bz;
    int slot = (MODE == 4) ? (bz >> 3) : 0;
    int w0 = blockIdx.x * CTW;
    int h0 = blockIdx.y * CTH;

    const uint2* wp  = wpk;
    const uint2* wp1 = nullptr;
    const float* bbase  = bias;
    const float* bbase1 = nullptr;
    float cw = 1.f, c0 = 0.f, c1 = 0.f;
    if (MODE == 4) {
        int e = sel[b*2 + slot];
        wp = wpk + e * WSET;
        bbase = bias + e * Cc;
        cw = cofsel[b*2 + slot];
    }
    if (MODE == 5) {
        int e0 = sel[b*2], e1 = sel[b*2 + 1];
        wp  = wpk + e0 * WSET;
        wp1 = wpk + e1 * WSET;
        bbase  = bias + e0 * Cc;
        bbase1 = bias + e1 * Cc;
        c0 = cofsel[b*2]; c1 = cofsel[b*2 + 1];
    }
    const float* inb0 = in + (size_t)b * PLANE;
    const float* inb1 = (MODE == 5) ? (add2 + (size_t)b * PLANE) : nullptr;

    unsigned wdst8[9];
    unsigned wsrc[9];
    unsigned swbase = (unsigned)__cvta_generic_to_shared(s_w);
    #pragma unroll
    for (int t = 0; t < 9; t++) {
        int i = tid + t*256;
        int q = i >> 6, oc = i & 63;
        wdst8[t] = (unsigned)((q*WPAD + oc) * 8);
        wsrc[t] = (unsigned)(q*64 + oc);
    }

    bool iact[3], ival[3];
    unsigned ioff[3];
    int ismem[3];
    #pragma unroll
    for (int t = 0; t < 3; t++) {
        int i = tid + t*256;
        iact[t] = (i < 4*INREAL);
        int kq  = i / INREAL;
        int rem = i - kq*INREAL;
        int rr = rem / INC;
        int cc = rem - rr*INC;
        int h = h0 - 1 + rr;
        int w = w0 - 1 + cc;
        ival[t] = iact[t] && ((unsigned)h < HWd) && ((unsigned)w < HWd);
        ismem[t] = kq*INPAD + rem;
        ioff[t] = ival[t] ? (unsigned)(kq*NPIX + h*HWd + w) : 0u;
    }

    float d[2][4][4];
    #pragma unroll
    for (int mt = 0; mt < 2; mt++)
        #pragma unroll
        for (int nt = 0; nt < 4; nt++)
            #pragma unroll
            for (int r = 0; r < 4; r++) d[mt][nt][r] = 0.f;

    // prologue: weights chunk 0 -> buf 0, input chunk 0 -> regs
    #pragma unroll
    for (int t = 0; t < 9; t++)
        cp_async8(swbase + wdst8[t], wp + wsrc[t]);
    cp_commit();

    float ipf0[3], ipf1[3];
    #pragma unroll
    for (int t = 0; t < 3; t++) {
        ipf0[t] = ival[t] ? inb0[ioff[t]] : 0.f;
        ipf1[t] = ival[t] ? inb0[ioff[t] + 4*NPIX] : 0.f;
    }

    #pragma unroll 1
    for (int ck = 0; ck < NCK; ck++) {
        __syncthreads();
        #pragma unroll
        for (int t = 0; t < 3; t++)
            if (iact[t]) s_in[ismem[t]] = make_uint2(f2tf32(ipf0[t]), f2tf32(ipf1[t]));
        if (ck < NCK-1) {
            int nx = ck + 1;
            // weights for chunk nx into alternate buffer
            unsigned bufoff = (unsigned)((nx & 1) * SW_CH * 8);
            const uint2* srcw = ((MODE == 5 && nx >= 8) ? wp1 : wp) + (nx & 7) * 2304;
            #pragma unroll
            for (int t = 0; t < 9; t++)
                cp_async8(swbase + bufoff + wdst8[t], srcw + wsrc[t]);
            cp_commit();
            // input for chunk nx
            const float* srci = (MODE == 5 && nx >= 8) ? inb1 : inb0;
            unsigned ib = (unsigned)((nx & 7) * 8*NPIX);
            #pragma unroll
            for (int t = 0; t < 3; t++) {
                if (ival[t]) {
                    ipf0[t] = srci[ioff[t] + ib];
                    ipf1[t] = srci[ioff[t] + ib + 4*NPIX];
                }
            }
            cp_wait1();
        } else {
            cp_wait0();
        }
        __syncthreads();

        const uint2* swc = s_w + (ck&1)*SW_CH;
        #pragma unroll
        for (int tap = 0; tap < 9; tap++) {
            int ky = tap / 3, kx = tap % 3;
            int abase = l4*INPAD + (wm2 + ky)*INC + kx + g;
            unsigned a[2][4];
            #pragma unroll
            for (int mt = 0; mt < 2; mt++) {
                uint2 p0 = s_in[abase + mt*INC];
                uint2 p1 = s_in[abase + mt*INC + 8];
                a[mt][0] = p0.x; a[mt][1] = p1.x; a[mt][2] = p0.y; a[mt][3] = p1.y;
            }
            int bb = (tap*4 + l4)*WPAD + n0 + g;
            unsigned bq[4][2];
            #pragma unroll
            for (int nt = 0; nt < 4; nt++) {
                uint2 q = swc[bb + nt*8];
                bq[nt][0] = q.x; bq[nt][1] = q.y;
            }
            #pragma unroll
            for (int mt = 0; mt < 2; mt++)
                #pragma unroll
                for (int nt = 0; nt < 4; nt++)
                    mma_tf32(d[mt][nt], a[mt], bq[nt]);
        }
    }

    // epilogue
    float csum = c0 + c1;
    float* dst4 = (MODE == 4 && slot) ? out2 : out;
    #pragma unroll
    for (int mt = 0; mt < 2; mt++) {
        int h = h0 + wm2 + mt;
        #pragma unroll
        for (int nt = 0; nt < 4; nt++) {
            int oc = n0 + nt*8 + l4*2;
            float bv0, bv1;
            if (MODE == 5) {
                bv0 = c0*bbase[oc]   + c1*bbase1[oc];
                bv1 = c0*bbase[oc+1] + c1*bbase1[oc+1];
            } else {
                bv0 = bbase[oc]; bv1 = bbase[oc+1];
            }
            size_t p0 = (size_t)b*PLANE + (size_t)oc*NPIX + (size_t)h*HWd;
            size_t p1 = p0 + NPIX;
            int wa = w0 + g, wb2 = wa + 8;
            float vv[4] = { d[mt][nt][0] + bv0, d[mt][nt][1] + bv1,
                            d[mt][nt][2] + bv0, d[mt][nt][3] + bv1 };
            size_t ix[4] = { p0 + wa, p1 + wa, p0 + wb2, p1 + wb2 };
            #pragma unroll
            for (int r = 0; r < 4; r++) {
                size_t idx = ix[r];
                float v = vv[r];
                if (MODE == 1) {
                    v += add1[idx] + add2[idx];
                } else if (MODE == 2) {
                    v += add1[idx];
                } else if (MODE == 3) {
                    float sp = spre[idx];
                    float sig = 1.f / (1.f + expf(-sp));
                    float s = CLAMPv * (2.f*sig - 1.f);
                    v += add1[idx] + add2[idx] * expf(s);
                } else if (MODE == 4) {
                    v = v > 0.f ? v : LEAKv * v;
                    v *= cw;
                } else if (MODE == 5) {
                    v += csum * add1[idx];
                }
                if (MODE == 4) dst4[idx] = v;
                else           out[idx] = v;
            }
        }
    }
}

// ---------------- 1x1 GEMM via TF32 MMA ----------------
#define GPAD 132

template<int IC>
__global__ __launch_bounds__(256)
void gemm1x1_mma(const float* __restrict__ inA, const float* __restrict__ inB,
                 const float* __restrict__ W, const float* __restrict__ bias,
                 float* __restrict__ outA, float* __restrict__ outB)
{
    __shared__ uint2 s_x[8 * GPAD];
    __shared__ uint2 s_w[8 * WPAD];

    int tid = threadIdx.x;
    int wid = tid >> 5;
    int lane = tid & 31;
    int l4 = lane & 3;
    int g  = lane >> 2;
    int warp_m = wid & 3;
    int warp_n = wid >> 2;
    int n0 = warp_n * 32;

    int b   = blockIdx.z;
    int oc0 = blockIdx.y * 64;
    int p0  = blockIdx.x * 128;

    float d[2][4][4];
    #pragma unroll
    for (int mt = 0; mt < 2; mt++)
        #pragma unroll
        for (int nt = 0; nt < 4; nt++)
            #pragma unroll
            for (int r = 0; r < 4; r++) d[mt][nt][r] = 0.f;

    for (int ch = 0; ch < IC; ch += 16) {
        for (int i = tid; i < 8*128; i += 256) {
            int q = i >> 7;
            int p = i & 127;
            int ic0 = ch + (q >> 2)*8 + (q & 3);
            unsigned v0, v1;
            if (inB != nullptr) {
                const float* s0 = (ic0 < 64) ? inA : inB;
                const float* s1 = (ic0+4 < 64) ? inA : inB;
                v0 = f2tf32(s0[(size_t)b*PLANE + (size_t)(ic0 & 63)*NPIX + p0 + p]);
                v1 = f2tf32(s1[(size_t)b*PLANE + (size_t)((ic0+4) & 63)*NPIX + p0 + p]);
            } else {
                v0 = f2tf32(inA[((size_t)b*IC + ic0)*NPIX + p0 + p]);
                v1 = f2tf32(inA[((size_t)b*IC + ic0 + 4)*NPIX + p0 + p]);
            }
            s_x[q*GPAD + p] = make_uint2(v0, v1);
        }
        for (int i = tid; i < 8*64; i += 256) {
            int q  = i & 7;
            int oc = i >> 3;
            int ic0 = ch + (q >> 2)*8 + (q & 3);
            size_t o = (size_t)(oc0 + oc)*IC + ic0;
            s_w[q*WPAD + oc] = make_uint2(f2tf32(W[o]), f2tf32(W[o + 4]));
        }
        __syncthreads();

        #pragma unroll
        for (int ks = 0; ks < 2; ks++) {
            int abase = (ks*4 + l4)*GPAD + warp_m*32 + g;
            unsigned a[2][4];
            #pragma unroll
            for (int mt = 0; mt < 2; mt++) {
                uint2 q0 = s_x[abase + mt*16];
                uint2 q1 = s_x[abase + mt*16 + 8];
                a[mt][0] = q0.x; a[mt][1] = q1.x; a[mt][2] = q0.y; a[mt][3] = q1.y;
            }
            int bb = (ks*4 + l4)*WPAD + n0 + g;
            unsigned bq[4][2];
            #pragma unroll
            for (int nt = 0; nt < 4; nt++) {
                uint2 q = s_w[bb + nt*8];
                bq[nt][0] = q.x; bq[nt][1] = q.y;
            }
            #pragma unroll
            for (int mt = 0; mt < 2; mt++)
                #pragma unroll
                for (int nt = 0; nt < 4; nt++)
                    mma_tf32(d[mt][nt], a[mt], bq[nt]);
        }
        __syncthreads();
    }

    #pragma unroll
    for (int mt = 0; mt < 2; mt++) {
        #pragma unroll
        for (int nt = 0; nt < 4; nt++) {
            int oc = oc0 + n0 + nt*8 + l4*2;
            float bv0 = bias ? bias[oc] : 0.f;
            float bv1 = bias ? bias[oc+1] : 0.f;
            float* dst = outA;
            int ocd = oc;
            if (outB != nullptr && oc >= 64) { dst = outB; ocd = oc - 64; }
            int pix = p0 + warp_m*32 + mt*16 + g;
            size_t q0 = (size_t)b*PLANE + (size_t)ocd*NPIX + pix;
            size_t q1 = q0 + NPIX;
            dst[q0]     = d[mt][nt][0] + bv0;
            dst[q1]     = d[mt][nt][1] + bv1;
            dst[q0 + 8] = d[mt][nt][2] + bv0;
            dst[q1 + 8] = d[mt][nt][3] + bv1;
        }
    }
}

// ---------------- instance norm (in-place) ----------------
__global__ __launch_bounds__(256)
void inorm_k(float* __restrict__ r, const float* __restrict__ nw, const float* __restrict__ nb)
{
    int bidx = blockIdx.x;
    int b = bidx >> 5, c = bidx & 31;
    float* p = r + (size_t)b*PLANE + (size_t)c*NPIX;
    int tid = threadIdx.x;
    float s = 0.f, s2 = 0.f;
    for (int i = tid; i < NPIX; i += 256) { float v = p[i]; s += v; s2 += v*v; }
    __shared__ float sh[256], sh2[256];
    sh[tid] = s; sh2[tid] = s2;
    __syncthreads();
    for (int st = 128; st; st >>= 1) {
        if (tid < st) { sh[tid] += sh[tid+st]; sh2[tid] += sh2[tid+st]; }
        __syncthreads();
    }
    float mean = sh[0] * (1.f/NPIX);
    float var = sh2[0] * (1.f/NPIX) - mean*mean;
    float inv = rsqrtf(var + EPSv);
    float ga = nw[c], be = nb[c];
    for (int i = tid; i < NPIX; i += 256)
        p[i] = (p[i] - mean) * inv * ga + be;
}

// ---------------- pool ----------------
__global__ __launch_bounds__(256)
void pool_k(const float* __restrict__ xf, float* __restrict__ g)
{
    int bc = blockIdx.x;
    const float* p = xf + (size_t)bc * NPIX;
    int tid = threadIdx.x;
    float mx = -1e30f, sm = 0.f;
    for (int i = tid; i < NPIX; i += 256) { float v = p[i]; mx = fmaxf(mx, v); sm += v; }
    __shared__ float smx[256], ssm[256];
    smx[tid] = mx; ssm[tid] = sm;
    __syncthreads();
    for (int st = 128; st; st >>= 1) {
        if (tid < st) { smx[tid] = fmaxf(smx[tid], smx[tid+st]); ssm[tid] += ssm[tid+st]; }
        __syncthreads();
    }
    if (tid == 0) g[bc] = smx[0] + ssm[0] * (1.f/NPIX);
}

// ---------------- gating ----------------
__global__ void gate_k(const float* __restrict__ g,
                       const float* __restrict__ gw0, const float* __restrict__ gb0,
                       const float* __restrict__ gw1, const float* __restrict__ gb1,
                       float* __restrict__ cof_out, int* __restrict__ sel,
                       float* __restrict__ cofsel)
{
    int b = threadIdx.x;
    if (b >= Bsz) return;
    float lg[4], noi[4];
    for (int e = 0; e < 4; e++) {
        float a0 = gb0[e], a1 = gb1[e];
        for (int c = 0; c < 64; c++) {
            float gv = g[b*64 + c];
            a0 += gw0[e*64 + c] * gv;
            a1 += gw1[e*64 + c] * gv;
        }
        lg[e] = a1 > 0.f ? a1 : LEAKv * a1;
        noi[e] = fmaxf(a0, 0.f) + log1pf(expf(-fabsf(a0)));
    }
    float m = 0.25f * (noi[0] + noi[1] + noi[2] + noi[3]);
    float var = 0.f;
    for (int e = 0; e < 4; e++) { float dd = noi[e] - m; var += dd*dd; }
    float sd = sqrtf(var / 3.f);
    float sc[4];
    for (int e = 0; e < 4; e++) sc[e] = lg[e] + (noi[e] - m) / sd;
    int i0 = 0;
    for (int e = 1; e < 4; e++) if (sc[e] > sc[i0]) i0 = e;
    int i1 = -1;
    for (int e = 0; e < 4; e++) {
        if (e == i0) continue;
        if (i1 < 0 || sc[e] > sc[i1]) i1 = e;
    }
    float mm = fmaxf(lg[i0], lg[i1]);
    float e0 = expf(lg[i0] - mm), e1 = expf(lg[i1] - mm);
    float c0 = e0 / (e0 + e1), c1 = e1 / (e0 + e1);
    if (cof_out) {
        for (int e = 0; e < 4; e++) cof_out[b*4 + e] = 0.f;
        cof_out[b*4 + i0] = c0;
        cof_out[b*4 + i1] = c1;
    }
    sel[b*2 + 0] = i0; sel[b*2 + 1] = i1;
    cofsel[b*2 + 0] = c0; cofsel[b*2 + 1] = c1;
}

// ---------------- launch ----------------
extern "C" void kernel_launch(void* const* d_in, const int* in_sizes, int n_in,
                              void* d_out, int out_size)
{
    const float* x       = (const float*)d_in[0];
    const float* winv    = (const float*)d_in[1];
    const float* blk_w1  = (const float*)d_in[2];
    const float* blk_b1  = (const float*)d_in[3];
    const float* blk_nw  = (const float*)d_in[4];
    const float* blk_nb  = (const float*)d_in[5];
    const float* blk_w2  = (const float*)d_in[6];
    const float* blk_b2  = (const float*)d_in[7];
    const float* fuse_w  = (const float*)d_in[8];
    const float* fuse_b  = (const float*)d_in[9];
    const float* gw0     = (const float*)d_in[10];
    const float* gb0     = (const float*)d_in[11];
    const float* gw1     = (const float*)d_in[12];
    const float* gb1     = (const float*)d_in[13];
    const float* ew1     = (const float*)d_in[14];
    const float* eb1     = (const float*)d_in[15];
    const float* ew2     = (const float*)d_in[16];
    const float* eb2     = (const float*)d_in[17];
    float* out = (float*)d_out;
    float* cof_out = ((size_t)out_size >= BS + Bsz*4) ? out + BS : nullptr;

    float *x1, *x2, *y1, *y2, *rb, *sb, *xf, *hb, *gv, *cofsel; int* sel; uint2* wpack;
    void* p;
    cudaGetSymbolAddress(&p, g_x1);  x1 = (float*)p;
    cudaGetSymbolAddress(&p, g_x2);  x2 = (float*)p;
    cudaGetSymbolAddress(&p, g_y1);  y1 = (float*)p;
    cudaGetSymbolAddress(&p, g_y2);  y2 = (float*)p;
    cudaGetSymbolAddress(&p, g_rb);  rb = (float*)p;
    cudaGetSymbolAddress(&p, g_sb);  sb = (float*)p;
    cudaGetSymbolAddress(&p, g_xf);  xf = (float*)p;
    cudaGetSymbolAddress(&p, g_hb);  hb = (float*)p;
    cudaGetSymbolAddress(&p, g_gv);  gv = (float*)p;
    cudaGetSymbolAddress(&p, g_sel); sel = (int*)p;
    cudaGetSymbolAddress(&p, g_cofsel); cofsel = (float*)p;
    cudaGetSymbolAddress(&p, g_wpack);  wpack = (uint2*)p;

    dim3 cgrid(HWd/CTW, HWd/CTH, Bsz);
    dim3 cgrid4(HWd/CTW, HWd/CTH, Bsz*2);   // merged expert conv1: (slot,b)
    dim3 wgrid(NPIX/128, 2, Bsz);
    dim3 fgrid(NPIX/128, 1, Bsz);

    pack_all<<<(14*WSET+255)/256, 256>>>(blk_w1, blk_w2, ew1, ew2, wpack);

    gemm1x1_mma<128><<<wgrid, 256>>>(x, nullptr, winv, nullptr, x1, x2);

    conv3x3_mma<0><<<cgrid, 256>>>(x2, wpack + 0*WSET, blk_b1 + 0*64, rb,
                                   nullptr, nullptr, nullptr, nullptr, nullptr, nullptr);
    inorm_k<<<Bsz*32, 256>>>(rb, blk_nw + 0*32, blk_nb + 0*32);
    conv3x3_mma<1><<<cgrid, 256>>>(rb, wpack + 3*WSET, blk_b2 + 0*64, y1,
                                   x2, x1, nullptr, nullptr, nullptr, nullptr);

    conv3x3_mma<0><<<cgrid, 256>>>(y1, wpack + 2*WSET, blk_b1 + 2*64, rb,
                                   nullptr, nullptr, nullptr, nullptr, nullptr, nullptr);
    inorm_k<<<Bsz*32, 256>>>(rb, blk_nw + 2*32, blk_nb + 2*32);
    conv3x3_mma<2><<<cgrid, 256>>>(rb, wpack + 5*WSET, blk_b2 + 2*64, sb,
                                   y1, nullptr, nullptr, nullptr, nullptr, nullptr);

    conv3x3_mma<0><<<cgrid, 256>>>(y1, wpack + 1*WSET, blk_b1 + 1*64, rb,
                                   nullptr, nullptr, nullptr, nullptr, nullptr, nullptr);
    inorm_k<<<Bsz*32, 256>>>(rb, blk_nw + 1*32, blk_nb + 1*32);
    conv3x3_mma<3><<<cgrid, 256>>>(rb, wpack + 4*WSET, blk_b2 + 1*64, y2,
                                   y1, x2, sb, nullptr, nullptr, nullptr);

    gemm1x1_mma<128><<<fgrid, 256>>>(y1, y2, fuse_w, fuse_b, xf, nullptr);

    pool_k<<<Bsz*64, 256>>>(xf, gv);
    gate_k<<<1, 32>>>(gv, gw0, gb0, gw1, gb1, cof_out, sel, cofsel);

    // experts: ONE conv1 launch (both slots; cof pre-scaled), ONE K=128 conv2 launch
    conv3x3_mma<4><<<cgrid4, 256>>>(xf, wpack + 6*WSET, eb1, hb,
                                    nullptr, nullptr, nullptr, sel, cofsel, rb);
    conv3x3_mma<5><<<cgrid, 256>>>(hb, wpack + 10*WSET, eb2, out,
                                   xf, rb, nullptr, sel, cofsel, nullptr);
}

// round 14
// speedup vs baseline: 1.2894x; 1.0924x over previous
#include <cuda_runtime.h>
#include <math.h>

#define Bsz 8
#define Cc 64
#define HWd 128
#define NPIX (HWd*HWd)
#define PLANE ((size_t)Cc*NPIX)
#define BS ((size_t)Bsz*Cc*NPIX)
#define LEAKv 0.2f
#define CLAMPv 0.8f
#define EPSv 1e-5f
#define CWS (64*64*9)

#define CTW 16
#define CTH 8
#define INC 18
#define INREAL 180
#define INPAD 196             // uint2 stride, 196 % 16 == 4
#define WPAD 68               // 68 % 16 == 4
#define SW_CH (36*WPAD)       // uint2 per weight smem buffer
#define WSET 18432            // uint2 per packed weight set

// ---------------- scratch ----------------
__device__ float g_x1[Bsz*Cc*NPIX];
__device__ float g_x2[Bsz*Cc*NPIX];
__device__ float g_y1[Bsz*Cc*NPIX];
__device__ float g_y2[Bsz*Cc*NPIX];
__device__ float g_rb[Bsz*Cc*NPIX];
__device__ float g_sb[Bsz*Cc*NPIX];
__device__ float g_xf[Bsz*Cc*NPIX];
__device__ float g_hb[Bsz*Cc*NPIX];
__device__ float g_gv[Bsz*Cc];
__device__ int   g_sel[Bsz*2];
__device__ float g_cofsel[Bsz*2];
__device__ uint2 g_wpack[14*WSET];

__device__ __forceinline__ unsigned f2tf32(float f) {
    unsigned r;
    asm("cvt.rna.tf32.f32 %0, %1;" : "=r"(r) : "f"(f));
    return r;
}

__device__ __forceinline__ void mma_tf32(float* d, const unsigned* a, const unsigned* b) {
    asm volatile(
        "mma.sync.aligned.m16n8k8.row.col.f32.tf32.tf32.f32 "
        "{%0,%1,%2,%3}, {%4,%5,%6,%7}, {%8,%9}, {%0,%1,%2,%3};"
        : "+f"(d[0]), "+f"(d[1]), "+f"(d[2]), "+f"(d[3])
        : "r"(a[0]), "r"(a[1]), "r"(a[2]), "r"(a[3]), "r"(b[0]), "r"(b[1]));
}

__device__ __forceinline__ void cp_async8(unsigned sdst, const void* gsrc) {
    asm volatile("cp.async.ca.shared.global [%0], [%1], 8;" :: "r"(sdst), "l"(gsrc));
}
__device__ __forceinline__ void cp_commit() { asm volatile("cp.async.commit_group;" ::: "memory"); }
__device__ __forceinline__ void cp_wait1()  { asm volatile("cp.async.wait_group 1;" ::: "memory"); }
__device__ __forceinline__ void cp_wait0()  { asm volatile("cp.async.wait_group 0;" ::: "memory"); }

// ---------------- single merged weight repack ----------------
__global__ void pack_all(const float* __restrict__ w1, const float* __restrict__ w2,
                         const float* __restrict__ e1, const float* __restrict__ e2,
                         uint2* __restrict__ dst)
{
    int i = blockIdx.x*blockDim.x + threadIdx.x;
    if (i >= 14*WSET) return;
    int s = i / WSET;
    int r = i % WSET;
    const float* src;
    if (s < 3)       src = w1 + (size_t)s * CWS;
    else if (s < 6)  src = w2 + (size_t)(s-3) * CWS;
    else if (s < 10) src = e1 + (size_t)(s-6) * CWS;
    else             src = e2 + (size_t)(s-10) * CWS;
    int ck  = r / 2304;
    int rem = r % 2304;
    int q = rem >> 6, oc = rem & 63;
    int kq = q & 3, tap = q >> 2;
    int ic = ck*8 + kq;
    dst[i] = make_uint2(f2tf32(src[(oc*64 + ic)*9 + tap]),
                        f2tf32(src[(oc*64 + ic + 4)*9 + tap]));
}

// ---------------- 3x3 conv: TF32 MMA + cp.async packed weights (R10 core, frozen) ----------------
// MODE 0: out = conv+bias
// MODE 1: out = conv+bias+add1+add2
// MODE 2: out = conv+bias+add1
// MODE 3: out = conv+bias+add1 + add2*exp(clamp*(2sig(spre)-1))
// MODE 4: MERGED expert conv1: z=(slot*8+b); dst[slot] = cof*lrelu(conv+b_e)
// MODE 5: MERGED expert conv2: K=128 (in: 0-7, add2: 8-15), weights e0/e1 per half
template<int MODE>
__global__ __launch_bounds__(256)
void conv3x3_mma(const float* __restrict__ in, const uint2* __restrict__ wpk,
                 const float* __restrict__ bias, float* __restrict__ out,
                 const float* __restrict__ add1, const float* __restrict__ add2,
                 const float* __restrict__ spre,
                 const int* __restrict__ sel, const float* __restrict__ cofsel,
                 float* __restrict__ out2)
{
    __shared__ uint2 s_in[4 * INPAD];
    __shared__ uint2 s_w[2 * SW_CH];

    const int NCK = (MODE == 5) ? 16 : 8;

    int tid = threadIdx.x;
    int wid = tid >> 5;
    int lane = tid & 31;
    int l4 = lane & 3;
    int g  = lane >> 2;
    int warp_m = wid & 3;
    int warp_n = wid >> 2;
    int wm2 = warp_m * 2;
    int n0 = warp_n * 32;

    int bz = blockIdx.z;
    int b    = (MODE == 4) ? (bz & 7) : bz;
    int slot = (MODE == 4) ? (bz >> 3) : 0;
    int w0 = blockIdx.x * CTW;
    int h0 = blockIdx.y * CTH;

    const uint2* wp  = wpk;
    const uint2* wp1 = nullptr;
    const float* bbase  = bias;
    const float* bbase1 = nullptr;
    float cw = 1.f, c0 = 0.f, c1 = 0.f;
    if (MODE == 4) {
        int e = sel[b*2 + slot];
        wp = wpk + e * WSET;
        bbase = bias + e * Cc;
        cw = cofsel[b*2 + slot];
    }
    if (MODE == 5) {
        int e0 = sel[b*2], e1 = sel[b*2 + 1];
        wp  = wpk + e0 * WSET;
        wp1 = wpk + e1 * WSET;
        bbase  = bias + e0 * Cc;
        bbase1 = bias + e1 * Cc;
        c0 = cofsel[b*2]; c1 = cofsel[b*2 + 1];
    }
    const float* inb0 = in + (size_t)b * PLANE;
    const float* inb1 = (MODE == 5) ? (add2 + (size_t)b * PLANE) : nullptr;

    unsigned wdst8[9];
    unsigned wsrc[9];
    unsigned swbase = (unsigned)__cvta_generic_to_shared(s_w);
    #pragma unroll
    for (int t = 0; t < 9; t++) {
        int i = tid + t*256;
        int q = i >> 6, oc = i & 63;
        wdst8[t] = (unsigned)((q*WPAD + oc) * 8);
        wsrc[t] = (unsigned)(q*64 + oc);
    }

    bool iact[3], ival[3];
    unsigned ioff[3];
    int ismem[3];
    #pragma unroll
    for (int t = 0; t < 3; t++) {
        int i = tid + t*256;
        iact[t] = (i < 4*INREAL);
        int kq  = i / INREAL;
        int rem = i - kq*INREAL;
        int rr = rem / INC;
        int cc = rem - rr*INC;
        int h = h0 - 1 + rr;
        int w = w0 - 1 + cc;
        ival[t] = iact[t] && ((unsigned)h < HWd) && ((unsigned)w < HWd);
        ismem[t] = kq*INPAD + rem;
        ioff[t] = ival[t] ? (unsigned)(kq*NPIX + h*HWd + w) : 0u;
    }

    float d[2][4][4];
    #pragma unroll
    for (int mt = 0; mt < 2; mt++)
        #pragma unroll
        for (int nt = 0; nt < 4; nt++)
            #pragma unroll
            for (int r = 0; r < 4; r++) d[mt][nt][r] = 0.f;

    #pragma unroll
    for (int t = 0; t < 9; t++)
        cp_async8(swbase + wdst8[t], wp + wsrc[t]);
    cp_commit();

    float ipf0[3], ipf1[3];
    #pragma unroll
    for (int t = 0; t < 3; t++) {
        ipf0[t] = ival[t] ? inb0[ioff[t]] : 0.f;
        ipf1[t] = ival[t] ? inb0[ioff[t] + 4*NPIX] : 0.f;
    }

    #pragma unroll 1
    for (int ck = 0; ck < NCK; ck++) {
        __syncthreads();
        #pragma unroll
        for (int t = 0; t < 3; t++)
            if (iact[t]) s_in[ismem[t]] = make_uint2(f2tf32(ipf0[t]), f2tf32(ipf1[t]));
        if (ck < NCK-1) {
            int nx = ck + 1;
            unsigned bufoff = (unsigned)((nx & 1) * SW_CH * 8);
            const uint2* srcw = ((MODE == 5 && nx >= 8) ? wp1 : wp) + (nx & 7) * 2304;
            #pragma unroll
            for (int t = 0; t < 9; t++)
                cp_async8(swbase + bufoff + wdst8[t], srcw + wsrc[t]);
            cp_commit();
            const float* srci = (MODE == 5 && nx >= 8) ? inb1 : inb0;
            unsigned ib = (unsigned)((nx & 7) * 8*NPIX);
            #pragma unroll
            for (int t = 0; t < 3; t++) {
                if (ival[t]) {
                    ipf0[t] = srci[ioff[t] + ib];
                    ipf1[t] = srci[ioff[t] + ib + 4*NPIX];
                }
            }
            cp_wait1();
        } else {
            cp_wait0();
        }
        __syncthreads();

        const uint2* swc = s_w + (ck&1)*SW_CH;
        #pragma unroll
        for (int tap = 0; tap < 9; tap++) {
            int ky = tap / 3, kx = tap % 3;
            int abase = l4*INPAD + (wm2 + ky)*INC + kx + g;
            unsigned a[2][4];
            #pragma unroll
            for (int mt = 0; mt < 2; mt++) {
                uint2 p0 = s_in[abase + mt*INC];
                uint2 p1 = s_in[abase + mt*INC + 8];
                a[mt][0] = p0.x; a[mt][1] = p1.x; a[mt][2] = p0.y; a[mt][3] = p1.y;
            }
            int bb = (tap*4 + l4)*WPAD + n0 + g;
            unsigned bq[4][2];
            #pragma unroll
            for (int nt = 0; nt < 4; nt++) {
                uint2 q = swc[bb + nt*8];
                bq[nt][0] = q.x; bq[nt][1] = q.y;
            }
            #pragma unroll
            for (int mt = 0; mt < 2; mt++)
                #pragma unroll
                for (int nt = 0; nt < 4; nt++)
                    mma_tf32(d[mt][nt], a[mt], bq[nt]);
        }
    }

    float csum = c0 + c1;
    float* dst4 = (MODE == 4 && slot) ? out2 : out;
    #pragma unroll
    for (int mt = 0; mt < 2; mt++) {
        int h = h0 + wm2 + mt;
        #pragma unroll
        for (int nt = 0; nt < 4; nt++) {
            int oc = n0 + nt*8 + l4*2;
            float bv0, bv1;
            if (MODE == 5) {
                bv0 = c0*bbase[oc]   + c1*bbase1[oc];
                bv1 = c0*bbase[oc+1] + c1*bbase1[oc+1];
            } else {
                bv0 = bbase[oc]; bv1 = bbase[oc+1];
            }
            size_t p0 = (size_t)b*PLANE + (size_t)oc*NPIX + (size_t)h*HWd;
            size_t p1 = p0 + NPIX;
            int wa = w0 + g, wb2 = wa + 8;
            float vv[4] = { d[mt][nt][0] + bv0, d[mt][nt][1] + bv1,
                            d[mt][nt][2] + bv0, d[mt][nt][3] + bv1 };
            size_t ix[4] = { p0 + wa, p1 + wa, p0 + wb2, p1 + wb2 };
            #pragma unroll
            for (int r = 0; r < 4; r++) {
                size_t idx = ix[r];
                float v = vv[r];
                if (MODE == 1) {
                    v += add1[idx] + add2[idx];
                } else if (MODE == 2) {
                    v += add1[idx];
                } else if (MODE == 3) {
                    float sp = spre[idx];
                    float sig = 1.f / (1.f + expf(-sp));
                    float s = CLAMPv * (2.f*sig - 1.f);
                    v += add1[idx] + add2[idx] * expf(s);
                } else if (MODE == 4) {
                    v = v > 0.f ? v : LEAKv * v;
                    v *= cw;
                } else if (MODE == 5) {
                    v += csum * add1[idx];
                }
                if (MODE == 4) dst4[idx] = v;
                else           out[idx] = v;
            }
        }
    }
}

// ---------------- 1x1 GEMM via TF32 MMA, hoisted indices + register prefetch ----------------
#define GPAD 132

template<int IC>
__global__ __launch_bounds__(256)
void gemm1x1_mma(const float* __restrict__ inA, const float* __restrict__ inB,
                 const float* __restrict__ W, const float* __restrict__ bias,
                 float* __restrict__ outA, float* __restrict__ outB)
{
    __shared__ uint2 s_x[8 * GPAD];
    __shared__ uint2 s_w[8 * WPAD];

    const int NCK = IC / 16;   // 8

    int tid = threadIdx.x;
    int wid = tid >> 5;
    int lane = tid & 31;
    int l4 = lane & 3;
    int g  = lane >> 2;
    int warp_m = wid & 3;
    int warp_n = wid >> 2;
    int n0 = warp_n * 32;

    int b   = blockIdx.z;
    int oc0 = blockIdx.y * 64;
    int p0  = blockIdx.x * 128;

    // hoisted fill geometry
    // activations: 4 slots/thread (8 rows x 128 px = 1024 uint2)
    int axsm[4];
    unsigned aoff[4];        // channel-relative offset (qoff*NPIX + p0 + p)
    #pragma unroll
    for (int t = 0; t < 4; t++) {
        int i = tid + t*256;
        int q = i >> 7, p = i & 127;
        int qoff = (q >> 2)*8 + (q & 3);
        axsm[t] = q*GPAD + p;
        aoff[t] = (unsigned)(qoff*NPIX + p0 + p);
    }
    // weights: 2 slots/thread (8 x 64 = 512 uint2)
    int wxsm[2];
    unsigned woff0[2];       // (oc0+oc)*IC + qoff, chunk adds 16
    #pragma unroll
    for (int t = 0; t < 2; t++) {
        int i = tid + t*256;
        int q = i & 7, oc = i >> 3;
        int qoff = (q >> 2)*8 + (q & 3);
        wxsm[t] = q*WPAD + oc;
        woff0[t] = (unsigned)((oc0 + oc)*IC + qoff);
    }

    const float* baseA = inA + ((size_t)b * (inB ? PLANE : (size_t)IC*NPIX));
    const float* baseB = inB ? (inB + (size_t)b * PLANE) : nullptr;

    float d[2][4][4];
    #pragma unroll
    for (int mt = 0; mt < 2; mt++)
        #pragma unroll
        for (int nt = 0; nt < 4; nt++)
            #pragma unroll
            for (int r = 0; r < 4; r++) d[mt][nt][r] = 0.f;

    // prefetch chunk 0
    float apf0[4], apf1[4], wpf0[2], wpf1[2];
    {
        const float* src = baseA;
        #pragma unroll
        for (int t = 0; t < 4; t++) {
            apf0[t] = src[aoff[t]];
            apf1[t] = src[aoff[t] + 4*NPIX];
        }
        #pragma unroll
        for (int t = 0; t < 2; t++) {
            wpf0[t] = W[woff0[t]];
            wpf1[t] = W[woff0[t] + 4];
        }
    }

    #pragma unroll 1
    for (int ck = 0; ck < NCK; ck++) {
        __syncthreads();
        #pragma unroll
        for (int t = 0; t < 4; t++)
            s_x[axsm[t]] = make_uint2(f2tf32(apf0[t]), f2tf32(apf1[t]));
        #pragma unroll
        for (int t = 0; t < 2; t++)
            s_w[wxsm[t]] = make_uint2(f2tf32(wpf0[t]), f2tf32(wpf1[t]));
        if (ck < NCK-1) {
            int nx = ck + 1;
            // chunks 0-3 from A, 4-7 from B (when split); channel base within plane
            const float* src = (baseB && nx >= 4) ? baseB : baseA;
            unsigned chrel = (unsigned)(((baseB ? (nx & 3) : nx) * 16) * NPIX);
            if (!baseB) chrel = (unsigned)(nx * 16 * NPIX);
            #pragma unroll
            for (int t = 0; t < 4; t++) {
                apf0[t] = src[chrel + aoff[t]];
                apf1[t] = src[chrel + aoff[t] + 4*NPIX];
            }
            unsigned wb = (unsigned)(nx * 16);
            #pragma unroll
            for (int t = 0; t < 2; t++) {
                wpf0[t] = W[woff0[t] + wb];
                wpf1[t] = W[woff0[t] + wb + 4];
            }
        }
        __syncthreads();

        #pragma unroll
        for (int ks = 0; ks < 2; ks++) {
            int abase = (ks*4 + l4)*GPAD + warp_m*32 + g;
            unsigned a[2][4];
            #pragma unroll
            for (int mt = 0; mt < 2; mt++) {
                uint2 q0 = s_x[abase + mt*16];
                uint2 q1 = s_x[abase + mt*16 + 8];
                a[mt][0] = q0.x; a[mt][1] = q1.x; a[mt][2] = q0.y; a[mt][3] = q1.y;
            }
            int bb = (ks*4 + l4)*WPAD + n0 + g;
            unsigned bq[4][2];
            #pragma unroll
            for (int nt = 0; nt < 4; nt++) {
                uint2 q = s_w[bb + nt*8];
                bq[nt][0] = q.x; bq[nt][1] = q.y;
            }
            #pragma unroll
            for (int mt = 0; mt < 2; mt++)
                #pragma unroll
                for (int nt = 0; nt < 4; nt++)
                    mma_tf32(d[mt][nt], a[mt], bq[nt]);
        }
    }

    #pragma unroll
    for (int mt = 0; mt < 2; mt++) {
        #pragma unroll
        for (int nt = 0; nt < 4; nt++) {
            int oc = oc0 + n0 + nt*8 + l4*2;
            float bv0 = bias ? bias[oc] : 0.f;
            float bv1 = bias ? bias[oc+1] : 0.f;
            float* dst = outA;
            int ocd = oc;
            if (outB != nullptr && oc >= 64) { dst = outB; ocd = oc - 64; }
            int pix = p0 + warp_m*32 + mt*16 + g;
            size_t q0 = (size_t)b*PLANE + (size_t)ocd*NPIX + pix;
            size_t q1 = q0 + NPIX;
            dst[q0]     = d[mt][nt][0] + bv0;
            dst[q1]     = d[mt][nt][1] + bv1;
            dst[q0 + 8] = d[mt][nt][2] + bv0;
            dst[q1 + 8] = d[mt][nt][3] + bv1;
        }
    }
}

// ---------------- instance norm (in-place, float4) ----------------
__global__ __launch_bounds__(256)
void inorm_k(float* __restrict__ r, const float* __restrict__ nw, const float* __restrict__ nb)
{
    int bidx = blockIdx.x;
    int b = bidx >> 5, c = bidx & 31;
    float4* p = (float4*)(r + (size_t)b*PLANE + (size_t)c*NPIX);
    int tid = threadIdx.x;
    float s = 0.f, s2 = 0.f;
    for (int i = tid; i < NPIX/4; i += 256) {
        float4 v = p[i];
        s  += (v.x + v.y) + (v.z + v.w);
        s2 += (v.x*v.x + v.y*v.y) + (v.z*v.z + v.w*v.w);
    }
    __shared__ float sh[256], sh2[256];
    sh[tid] = s; sh2[tid] = s2;
    __syncthreads();
    for (int st = 128; st; st >>= 1) {
        if (tid < st) { sh[tid] += sh[tid+st]; sh2[tid] += sh2[tid+st]; }
        __syncthreads();
    }
    float mean = sh[0] * (1.f/NPIX);
    float var = sh2[0] * (1.f/NPIX) - mean*mean;
    float inv = rsqrtf(var + EPSv);
    float sc = inv * nw[c];
    float sh_ = nb[c] - mean * sc;
    for (int i = tid; i < NPIX/4; i += 256) {
        float4 v = p[i];
        v.x = fmaf(v.x, sc, sh_);
        v.y = fmaf(v.y, sc, sh_);
        v.z = fmaf(v.z, sc, sh_);
        v.w = fmaf(v.w, sc, sh_);
        p[i] = v;
    }
}

// ---------------- pool (float4) ----------------
__global__ __launch_bounds__(256)
void pool_k(const float* __restrict__ xf, float* __restrict__ g)
{
    int bc = blockIdx.x;
    const float4* p = (const float4*)(xf + (size_t)bc * NPIX);
    int tid = threadIdx.x;
    float mx = -1e30f, sm = 0.f;
    for (int i = tid; i < NPIX/4; i += 256) {
        float4 v = p[i];
        mx = fmaxf(mx, fmaxf(fmaxf(v.x, v.y), fmaxf(v.z, v.w)));
        sm += (v.x + v.y) + (v.z + v.w);
    }
    __shared__ float smx[256], ssm[256];
    smx[tid] = mx; ssm[tid] = sm;
    __syncthreads();
    for (int st = 128; st; st >>= 1) {
        if (tid < st) { smx[tid] = fmaxf(smx[tid], smx[tid+st]); ssm[tid] += ssm[tid+st]; }
        __syncthreads();
    }
    if (tid == 0) g[bc] = smx[0] + ssm[0] * (1.f/NPIX);
}

// ---------------- gating ----------------
__global__ void gate_k(const float* __restrict__ g,
                       const float* __restrict__ gw0, const float* __restrict__ gb0,
                       const float* __restrict__ gw1, const float* __restrict__ gb1,
                       float* __restrict__ cof_out, int* __restrict__ sel,
                       float* __restrict__ cofsel)
{
    int b = threadIdx.x;
    if (b >= Bsz) return;
    float lg[4], noi[4];
    for (int e = 0; e < 4; e++) {
        float a0 = gb0[e], a1 = gb1[e];
        for (int c = 0; c < 64; c++) {
            float gv = g[b*64 + c];
            a0 += gw0[e*64 + c] * gv;
            a1 += gw1[e*64 + c] * gv;
        }
        lg[e] = a1 > 0.f ? a1 : LEAKv * a1;
        noi[e] = fmaxf(a0, 0.f) + log1pf(expf(-fabsf(a0)));
    }
    float m = 0.25f * (noi[0] + noi[1] + noi[2] + noi[3]);
    float var = 0.f;
    for (int e = 0; e < 4; e++) { float dd = noi[e] - m; var += dd*dd; }
    float sd = sqrtf(var / 3.f);
    float sc[4];
    for (int e = 0; e < 4; e++) sc[e] = lg[e] + (noi[e] - m) / sd;
    int i0 = 0;
    for (int e = 1; e < 4; e++) if (sc[e] > sc[i0]) i0 = e;
    int i1 = -1;
    for (int e = 0; e < 4; e++) {
        if (e == i0) continue;
        if (i1 < 0 || sc[e] > sc[i1]) i1 = e;
    }
    float mm = fmaxf(lg[i0], lg[i1]);
    float e0 = expf(lg[i0] - mm), e1 = expf(lg[i1] - mm);
    float c0 = e0 / (e0 + e1), c1 = e1 / (e0 + e1);
    if (cof_out) {
        for (int e = 0; e < 4; e++) cof_out[b*4 + e] = 0.f;
        cof_out[b*4 + i0] = c0;
        cof_out[b*4 + i1] = c1;
    }
    sel[b*2 + 0] = i0; sel[b*2 + 1] = i1;
    cofsel[b*2 + 0] = c0; cofsel[b*2 + 1] = c1;
}

// ---------------- launch ----------------
extern "C" void kernel_launch(void* const* d_in, const int* in_sizes, int n_in,
                              void* d_out, int out_size)
{
    const float* x       = (const float*)d_in[0];
    const float* winv    = (const float*)d_in[1];
    const float* blk_w1  = (const float*)d_in[2];
    const float* blk_b1  = (const float*)d_in[3];
    const float* blk_nw  = (const float*)d_in[4];
    const float* blk_nb  = (const float*)d_in[5];
    const float* blk_w2  = (const float*)d_in[6];
    const float* blk_b2  = (const float*)d_in[7];
    const float* fuse_w  = (const float*)d_in[8];
    const float* fuse_b  = (const float*)d_in[9];
    const float* gw0     = (const float*)d_in[10];
    const float* gb0     = (const float*)d_in[11];
    const float* gw1     = (const float*)d_in[12];
    const float* gb1     = (const float*)d_in[13];
    const float* ew1     = (const float*)d_in[14];
    const float* eb1     = (const float*)d_in[15];
    const float* ew2     = (const float*)d_in[16];
    const float* eb2     = (const float*)d_in[17];
    float* out = (float*)d_out;
    float* cof_out = ((size_t)out_size >= BS + Bsz*4) ? out + BS : nullptr;

    float *x1, *x2, *y1, *y2, *rb, *sb, *xf, *hb, *gv, *cofsel; int* sel; uint2* wpack;
    void* p;
    cudaGetSymbolAddress(&p, g_x1);  x1 = (float*)p;
    cudaGetSymbolAddress(&p, g_x2);  x2 = (float*)p;
    cudaGetSymbolAddress(&p, g_y1);  y1 = (float*)p;
    cudaGetSymbolAddress(&p, g_y2);  y2 = (float*)p;
    cudaGetSymbolAddress(&p, g_rb);  rb = (float*)p;
    cudaGetSymbolAddress(&p, g_sb);  sb = (float*)p;
    cudaGetSymbolAddress(&p, g_xf);  xf = (float*)p;
    cudaGetSymbolAddress(&p, g_hb);  hb = (float*)p;
    cudaGetSymbolAddress(&p, g_gv);  gv = (float*)p;
    cudaGetSymbolAddress(&p, g_sel); sel = (int*)p;
    cudaGetSymbolAddress(&p, g_cofsel); cofsel = (float*)p;
    cudaGetSymbolAddress(&p, g_wpack);  wpack = (uint2*)p;

    dim3 cgrid(HWd/CTW, HWd/CTH, Bsz);
    dim3 cgrid4(HWd/CTW, HWd/CTH, Bsz*2);
    dim3 wgrid(NPIX/128, 2, Bsz);
    dim3 fgrid(NPIX/128, 1, Bsz);

    pack_all<<<(14*WSET+255)/256, 256>>>(blk_w1, blk_w2, ew1, ew2, wpack);

    gemm1x1_mma<128><<<wgrid, 256>>>(x, nullptr, winv, nullptr, x1, x2);

    conv3x3_mma<0><<<cgrid, 256>>>(x2, wpack + 0*WSET, blk_b1 + 0*64, rb,
                                   nullptr, nullptr, nullptr, nullptr, nullptr, nullptr);
    inorm_k<<<Bsz*32, 256>>>(rb, blk_nw + 0*32, blk_nb + 0*32);
    conv3x3_mma<1><<<cgrid, 256>>>(rb, wpack + 3*WSET, blk_b2 + 0*64, y1,
                                   x2, x1, nullptr, nullptr, nullptr, nullptr);

    conv3x3_mma<0><<<cgrid, 256>>>(y1, wpack + 2*WSET, blk_b1 + 2*64, rb,
                                   nullptr, nullptr, nullptr, nullptr, nullptr, nullptr);
    inorm_k<<<Bsz*32, 256>>>(rb, blk_nw + 2*32, blk_nb + 2*32);
    conv3x3_mma<2><<<cgrid, 256>>>(rb, wpack + 5*WSET, blk_b2 + 2*64, sb,
                                   y1, nullptr, nullptr, nullptr, nullptr, nullptr);

    conv3x3_mma<0><<<cgrid, 256>>>(y1, wpack + 1*WSET, blk_b1 + 1*64, rb,
                                   nullptr, nullptr, nullptr, nullptr, nullptr, nullptr);
    inorm_k<<<Bsz*32, 256>>>(rb, blk_nw + 1*32, blk_nb + 1*32);
    conv3x3_mma<3><<<cgrid, 256>>>(rb, wpack + 4*WSET, blk_b2 + 1*64, y2,
                                   y1, x2, sb, nullptr, nullptr, nullptr);

    gemm1x1_mma<128><<<fgrid, 256>>>(y1, y2, fuse_w, fuse_b, xf, nullptr);

    pool_k<<<Bsz*64, 256>>>(xf, gv);
    gate_k<<<1, 32>>>(gv, gw0, gb0, gw1, gb1, cof_out, sel, cofsel);

    conv3x3_mma<4><<<cgrid4, 256>>>(xf, wpack + 6*WSET, eb1, hb,
                                    nullptr, nullptr, nullptr, sel, cofsel, rb);
    conv3x3_mma<5><<<cgrid, 256>>>(hb, wpack + 10*WSET, eb2, out,
                                   xf, rb, nullptr, sel, cofsel, nullptr);
}

// round 15
// speedup vs baseline: 1.3119x; 1.0174x over previous
#include <cuda_runtime.h>
#include <math.h>

#define Bsz 8
#define Cc 64
#define HWd 128
#define NPIX (HWd*HWd)
#define PLANE ((size_t)Cc*NPIX)
#define BS ((size_t)Bsz*Cc*NPIX)
#define LEAKv 0.2f
#define CLAMPv 0.8f
#define EPSv 1e-5f
#define CWS (64*64*9)

#define CTW 16
#define CTH 8
#define INC 18
#define INREAL 180
#define INPAD 196
#define WPAD 68
#define SW_CH (36*WPAD)
#define WSET 18432

// ---------------- scratch ----------------
__device__ float g_x1[Bsz*Cc*NPIX];
__device__ float g_x2[Bsz*Cc*NPIX];
__device__ float g_y1[Bsz*Cc*NPIX];
__device__ float g_y2[Bsz*Cc*NPIX];
__device__ float g_rb[Bsz*Cc*NPIX];
__device__ float g_sb[Bsz*Cc*NPIX];
__device__ float g_xf[Bsz*Cc*NPIX];
__device__ float g_hb[Bsz*Cc*NPIX];
__device__ float g_gv[Bsz*Cc];
__device__ int   g_sel[Bsz*2];
__device__ float g_cofsel[Bsz*2];
__device__ uint2 g_wpack[14*WSET];

__device__ __forceinline__ unsigned f2tf32(float f) {
    unsigned r;
    asm("cvt.rna.tf32.f32 %0, %1;" : "=r"(r) : "f"(f));
    return r;
}

__device__ __forceinline__ void mma_tf32(float* d, const unsigned* a, const unsigned* b) {
    asm volatile(
        "mma.sync.aligned.m16n8k8.row.col.f32.tf32.tf32.f32 "
        "{%0,%1,%2,%3}, {%4,%5,%6,%7}, {%8,%9}, {%0,%1,%2,%3};"
        : "+f"(d[0]), "+f"(d[1]), "+f"(d[2]), "+f"(d[3])
        : "r"(a[0]), "r"(a[1]), "r"(a[2]), "r"(a[3]), "r"(b[0]), "r"(b[1]));
}

__device__ __forceinline__ void cp_async8(unsigned sdst, const void* gsrc) {
    asm volatile("cp.async.ca.shared.global [%0], [%1], 8;" :: "r"(sdst), "l"(gsrc));
}
__device__ __forceinline__ void cp_commit() { asm volatile("cp.async.commit_group;" ::: "memory"); }
__device__ __forceinline__ void cp_wait1()  { asm volatile("cp.async.wait_group 1;" ::: "memory"); }
__device__ __forceinline__ void cp_wait0()  { asm volatile("cp.async.wait_group 0;" ::: "memory"); }

// ---------------- single merged weight repack ----------------
__global__ void pack_all(const float* __restrict__ w1, const float* __restrict__ w2,
                         const float* __restrict__ e1, const float* __restrict__ e2,
                         uint2* __restrict__ dst)
{
    int i = blockIdx.x*blockDim.x + threadIdx.x;
    if (i >= 14*WSET) return;
    int s = i / WSET;
    int r = i % WSET;
    const float* src;
    if (s < 3)       src = w1 + (size_t)s * CWS;
    else if (s < 6)  src = w2 + (size_t)(s-3) * CWS;
    else if (s < 10) src = e1 + (size_t)(s-6) * CWS;
    else             src = e2 + (size_t)(s-10) * CWS;
    int ck  = r / 2304;
    int rem = r % 2304;
    int q = rem >> 6, oc = rem & 63;
    int kq = q & 3, tap = q >> 2;
    int ic = ck*8 + kq;
    dst[i] = make_uint2(f2tf32(src[(oc*64 + ic)*9 + tap]),
                        f2tf32(src[(oc*64 + ic + 4)*9 + tap]));
}

// ---------------- 3x3 conv: TF32 MMA (R10 core, 3 CTA/SM target) ----------------
// MODE 0: out = conv+bias
// MODE 1: out = conv+bias+add1+add2
// MODE 2: out = conv+bias+add1
// MODE 3: out = conv+bias+add1 + add2*exp(clamp*(2sig(spre)-1))
// MODE 4: MERGED expert conv1: z=(slot*8+b); dst[slot] = cof*lrelu(conv+b_e)
// MODE 5: MERGED expert conv2: K=128 (in: 0-7, add2: 8-15), weights e0/e1 per half
template<int MODE>
__global__ __launch_bounds__(256, 3)
void conv3x3_mma(const float* __restrict__ in, const uint2* __restrict__ wpk,
                 const float* __restrict__ bias, float* __restrict__ out,
                 const float* __restrict__ add1, const float* __restrict__ add2,
                 const float* __restrict__ spre,
                 const int* __restrict__ sel, const float* __restrict__ cofsel,
                 float* __restrict__ out2)
{
    __shared__ uint2 s_in[4 * INPAD];
    __shared__ uint2 s_w[2 * SW_CH];

    const int NCK = (MODE == 5) ? 16 : 8;

    int tid = threadIdx.x;
    int wid = tid >> 5;
    int lane = tid & 31;
    int l4 = lane & 3;
    int g  = lane >> 2;
    int warp_m = wid & 3;
    int warp_n = wid >> 2;
    int wm2 = warp_m * 2;
    int n0 = warp_n * 32;

    int bz = blockIdx.z;
    int b    = (MODE == 4) ? (bz & 7) : bz;
    int slot = (MODE == 4) ? (bz >> 3) : 0;
    int w0 = blockIdx.x * CTW;
    int h0 = blockIdx.y * CTH;

    const uint2* wp  = wpk;
    const uint2* wp1 = nullptr;
    const float* bbase  = bias;
    const float* bbase1 = nullptr;
    float cw = 1.f, c0 = 0.f, c1 = 0.f;
    if (MODE == 4) {
        int e = sel[b*2 + slot];
        wp = wpk + e * WSET;
        bbase = bias + e * Cc;
        cw = cofsel[b*2 + slot];
    }
    if (MODE == 5) {
        int e0 = sel[b*2], e1 = sel[b*2 + 1];
        wp  = wpk + e0 * WSET;
        wp1 = wpk + e1 * WSET;
        bbase  = bias + e0 * Cc;
        bbase1 = bias + e1 * Cc;
        c0 = cofsel[b*2]; c1 = cofsel[b*2 + 1];
    }
    const float* inb0 = in + (size_t)b * PLANE;
    const float* inb1 = (MODE == 5) ? (add2 + (size_t)b * PLANE) : nullptr;

    unsigned wdst8[9];
    unsigned wsrc[9];
    unsigned swbase = (unsigned)__cvta_generic_to_shared(s_w);
    #pragma unroll
    for (int t = 0; t < 9; t++) {
        int i = tid + t*256;
        int q = i >> 6, oc = i & 63;
        wdst8[t] = (unsigned)((q*WPAD + oc) * 8);
        wsrc[t] = (unsigned)(q*64 + oc);
    }

    bool iact[3], ival[3];
    unsigned ioff[3];
    int ismem[3];
    #pragma unroll
    for (int t = 0; t < 3; t++) {
        int i = tid + t*256;
        iact[t] = (i < 4*INREAL);
        int kq  = i / INREAL;
        int rem = i - kq*INREAL;
        int rr = rem / INC;
        int cc = rem - rr*INC;
        int h = h0 - 1 + rr;
        int w = w0 - 1 + cc;
        ival[t] = iact[t] && ((unsigned)h < HWd) && ((unsigned)w < HWd);
        ismem[t] = kq*INPAD + rem;
        ioff[t] = ival[t] ? (unsigned)(kq*NPIX + h*HWd + w) : 0u;
    }

    float d[2][4][4];
    #pragma unroll
    for (int mt = 0; mt < 2; mt++)
        #pragma unroll
        for (int nt = 0; nt < 4; nt++)
            #pragma unroll
            for (int r = 0; r < 4; r++) d[mt][nt][r] = 0.f;

    #pragma unroll
    for (int t = 0; t < 9; t++)
        cp_async8(swbase + wdst8[t], wp + wsrc[t]);
    cp_commit();

    float ipf0[3], ipf1[3];
    #pragma unroll
    for (int t = 0; t < 3; t++) {
        ipf0[t] = ival[t] ? inb0[ioff[t]] : 0.f;
        ipf1[t] = ival[t] ? inb0[ioff[t] + 4*NPIX] : 0.f;
    }

    #pragma unroll 1
    for (int ck = 0; ck < NCK; ck++) {
        __syncthreads();
        #pragma unroll
        for (int t = 0; t < 3; t++)
            if (iact[t]) s_in[ismem[t]] = make_uint2(f2tf32(ipf0[t]), f2tf32(ipf1[t]));
        if (ck < NCK-1) {
            int nx = ck + 1;
            unsigned bufoff = (unsigned)((nx & 1) * SW_CH * 8);
            const uint2* srcw = ((MODE == 5 && nx >= 8) ? wp1 : wp) + (nx & 7) * 2304;
            #pragma unroll
            for (int t = 0; t < 9; t++)
                cp_async8(swbase + bufoff + wdst8[t], srcw + wsrc[t]);
            cp_commit();
            const float* srci = (MODE == 5 && nx >= 8) ? inb1 : inb0;
            unsigned ib = (unsigned)((nx & 7) * 8*NPIX);
            #pragma unroll
            for (int t = 0; t < 3; t++) {
                if (ival[t]) {
                    ipf0[t] = srci[ioff[t] + ib];
                    ipf1[t] = srci[ioff[t] + ib + 4*NPIX];
                }
            }
            cp_wait1();
        } else {
            cp_wait0();
        }
        __syncthreads();

        const uint2* swc = s_w + (ck&1)*SW_CH;
        #pragma unroll
        for (int tap = 0; tap < 9; tap++) {
            int ky = tap / 3, kx = tap % 3;
            int abase = l4*INPAD + (wm2 + ky)*INC + kx + g;
            unsigned a[2][4];
            #pragma unroll
            for (int mt = 0; mt < 2; mt++) {
                uint2 p0 = s_in[abase + mt*INC];
                uint2 p1 = s_in[abase + mt*INC + 8];
                a[mt][0] = p0.x; a[mt][1] = p1.x; a[mt][2] = p0.y; a[mt][3] = p1.y;
            }
            int bb = (tap*4 + l4)*WPAD + n0 + g;
            unsigned bq[4][2];
            #pragma unroll
            for (int nt = 0; nt < 4; nt++) {
                uint2 q = swc[bb + nt*8];
                bq[nt][0] = q.x; bq[nt][1] = q.y;
            }
            #pragma unroll
            for (int mt = 0; mt < 2; mt++)
                #pragma unroll
                for (int nt = 0; nt < 4; nt++)
                    mma_tf32(d[mt][nt], a[mt], bq[nt]);
        }
    }

    float csum = c0 + c1;
    float* dst4 = (MODE == 4 && slot) ? out2 : out;
    #pragma unroll
    for (int mt = 0; mt < 2; mt++) {
        int h = h0 + wm2 + mt;
        #pragma unroll
        for (int nt = 0; nt < 4; nt++) {
            int oc = n0 + nt*8 + l4*2;
            float bv0, bv1;
            if (MODE == 5) {
                bv0 = c0*bbase[oc]   + c1*bbase1[oc];
                bv1 = c0*bbase[oc+1] + c1*bbase1[oc+1];
            } else {
                bv0 = bbase[oc]; bv1 = bbase[oc+1];
            }
            size_t p0 = (size_t)b*PLANE + (size_t)oc*NPIX + (size_t)h*HWd;
            size_t p1 = p0 + NPIX;
            int wa = w0 + g, wb2 = wa + 8;
            float vv[4] = { d[mt][nt][0] + bv0, d[mt][nt][1] + bv1,
                            d[mt][nt][2] + bv0, d[mt][nt][3] + bv1 };
            size_t ix[4] = { p0 + wa, p1 + wa, p0 + wb2, p1 + wb2 };
            #pragma unroll
            for (int r = 0; r < 4; r++) {
                size_t idx = ix[r];
                float v = vv[r];
                if (MODE == 1) {
                    v += add1[idx] + add2[idx];
                } else if (MODE == 2) {
                    v += add1[idx];
                } else if (MODE == 3) {
                    float sp = spre[idx];
                    float sig = 1.f / (1.f + expf(-sp));
                    float s = CLAMPv * (2.f*sig - 1.f);
                    v += add1[idx] + add2[idx] * expf(s);
                } else if (MODE == 4) {
                    v = v > 0.f ? v : LEAKv * v;
                    v *= cw;
                } else if (MODE == 5) {
                    v += csum * add1[idx];
                }
                if (MODE == 4) dst4[idx] = v;
                else           out[idx] = v;
            }
        }
    }
}

// ---------------- 1x1 GEMM via TF32 MMA (R14, kept) ----------------
#define GPAD 132

template<int IC>
__global__ __launch_bounds__(256)
void gemm1x1_mma(const float* __restrict__ inA, const float* __restrict__ inB,
                 const float* __restrict__ W, const float* __restrict__ bias,
                 float* __restrict__ outA, float* __restrict__ outB)
{
    __shared__ uint2 s_x[8 * GPAD];
    __shared__ uint2 s_w[8 * WPAD];

    const int NCK = IC / 16;

    int tid = threadIdx.x;
    int wid = tid >> 5;
    int lane = tid & 31;
    int l4 = lane & 3;
    int g  = lane >> 2;
    int warp_m = wid & 3;
    int warp_n = wid >> 2;
    int n0 = warp_n * 32;

    int b   = blockIdx.z;
    int oc0 = blockIdx.y * 64;
    int p0  = blockIdx.x * 128;

    int axsm[4];
    unsigned aoff[4];
    #pragma unroll
    for (int t = 0; t < 4; t++) {
        int i = tid + t*256;
        int q = i >> 7, p = i & 127;
        int qoff = (q >> 2)*8 + (q & 3);
        axsm[t] = q*GPAD + p;
        aoff[t] = (unsigned)(qoff*NPIX + p0 + p);
    }
    int wxsm[2];
    unsigned woff0[2];
    #pragma unroll
    for (int t = 0; t < 2; t++) {
        int i = tid + t*256;
        int q = i & 7, oc = i >> 3;
        int qoff = (q >> 2)*8 + (q & 3);
        wxsm[t] = q*WPAD + oc;
        woff0[t] = (unsigned)((oc0 + oc)*IC + qoff);
    }

    const float* baseA = inA + ((size_t)b * (inB ? PLANE : (size_t)IC*NPIX));
    const float* baseB = inB ? (inB + (size_t)b * PLANE) : nullptr;

    float d[2][4][4];
    #pragma unroll
    for (int mt = 0; mt < 2; mt++)
        #pragma unroll
        for (int nt = 0; nt < 4; nt++)
            #pragma unroll
            for (int r = 0; r < 4; r++) d[mt][nt][r] = 0.f;

    float apf0[4], apf1[4], wpf0[2], wpf1[2];
    {
        const float* src = baseA;
        #pragma unroll
        for (int t = 0; t < 4; t++) {
            apf0[t] = src[aoff[t]];
            apf1[t] = src[aoff[t] + 4*NPIX];
        }
        #pragma unroll
        for (int t = 0; t < 2; t++) {
            wpf0[t] = W[woff0[t]];
            wpf1[t] = W[woff0[t] + 4];
        }
    }

    #pragma unroll 1
    for (int ck = 0; ck < NCK; ck++) {
        __syncthreads();
        #pragma unroll
        for (int t = 0; t < 4; t++)
            s_x[axsm[t]] = make_uint2(f2tf32(apf0[t]), f2tf32(apf1[t]));
        #pragma unroll
        for (int t = 0; t < 2; t++)
            s_w[wxsm[t]] = make_uint2(f2tf32(wpf0[t]), f2tf32(wpf1[t]));
        if (ck < NCK-1) {
            int nx = ck + 1;
            const float* src = (baseB && nx >= 4) ? baseB : baseA;
            unsigned chrel;
            if (baseB) chrel = (unsigned)(((nx & 3) * 16) * NPIX);
            else       chrel = (unsigned)(nx * 16 * NPIX);
            #pragma unroll
            for (int t = 0; t < 4; t++) {
                apf0[t] = src[chrel + aoff[t]];
                apf1[t] = src[chrel + aoff[t] + 4*NPIX];
            }
            unsigned wb = (unsigned)(nx * 16);
            #pragma unroll
            for (int t = 0; t < 2; t++) {
                wpf0[t] = W[woff0[t] + wb];
                wpf1[t] = W[woff0[t] + wb + 4];
            }
        }
        __syncthreads();

        #pragma unroll
        for (int ks = 0; ks < 2; ks++) {
            int abase = (ks*4 + l4)*GPAD + warp_m*32 + g;
            unsigned a[2][4];
            #pragma unroll
            for (int mt = 0; mt < 2; mt++) {
                uint2 q0 = s_x[abase + mt*16];
                uint2 q1 = s_x[abase + mt*16 + 8];
                a[mt][0] = q0.x; a[mt][1] = q1.x; a[mt][2] = q0.y; a[mt][3] = q1.y;
            }
            int bb = (ks*4 + l4)*WPAD + n0 + g;
            unsigned bq[4][2];
            #pragma unroll
            for (int nt = 0; nt < 4; nt++) {
                uint2 q = s_w[bb + nt*8];
                bq[nt][0] = q.x; bq[nt][1] = q.y;
            }
            #pragma unroll
            for (int mt = 0; mt < 2; mt++)
                #pragma unroll
                for (int nt = 0; nt < 4; nt++)
                    mma_tf32(d[mt][nt], a[mt], bq[nt]);
        }
    }

    #pragma unroll
    for (int mt = 0; mt < 2; mt++) {
        #pragma unroll
        for (int nt = 0; nt < 4; nt++) {
            int oc = oc0 + n0 + nt*8 + l4*2;
            float bv0 = bias ? bias[oc] : 0.f;
            float bv1 = bias ? bias[oc+1] : 0.f;
            float* dst = outA;
            int ocd = oc;
            if (outB != nullptr && oc >= 64) { dst = outB; ocd = oc - 64; }
            int pix = p0 + warp_m*32 + mt*16 + g;
            size_t q0 = (size_t)b*PLANE + (size_t)ocd*NPIX + pix;
            size_t q1 = q0 + NPIX;
            dst[q0]     = d[mt][nt][0] + bv0;
            dst[q1]     = d[mt][nt][1] + bv1;
            dst[q0 + 8] = d[mt][nt][2] + bv0;
            dst[q1 + 8] = d[mt][nt][3] + bv1;
        }
    }
}

// ---------------- instance norm (in-place, float4, fully unrolled) ----------------
__global__ __launch_bounds__(256)
void inorm_k(float* __restrict__ r, const float* __restrict__ nw, const float* __restrict__ nb)
{
    int bidx = blockIdx.x;
    int b = bidx >> 5, c = bidx & 31;
    float4* p = (float4*)(r + (size_t)b*PLANE + (size_t)c*NPIX);
    int tid = threadIdx.x;
    float4 v[16];
    #pragma unroll
    for (int t = 0; t < 16; t++) v[t] = p[tid + t*256];
    float s = 0.f, s2 = 0.f;
    #pragma unroll
    for (int t = 0; t < 16; t++) {
        s  += (v[t].x + v[t].y) + (v[t].z + v[t].w);
        s2 += (v[t].x*v[t].x + v[t].y*v[t].y) + (v[t].z*v[t].z + v[t].w*v[t].w);
    }
    __shared__ float sh[256], sh2[256];
    sh[tid] = s; sh2[tid] = s2;
    __syncthreads();
    for (int st = 128; st; st >>= 1) {
        if (tid < st) { sh[tid] += sh[tid+st]; sh2[tid] += sh2[tid+st]; }
        __syncthreads();
    }
    float mean = sh[0] * (1.f/NPIX);
    float var = sh2[0] * (1.f/NPIX) - mean*mean;
    float inv = rsqrtf(var + EPSv);
    float sc = inv * nw[c];
    float sh_ = nb[c] - mean * sc;
    #pragma unroll
    for (int t = 0; t < 16; t++) {
        float4 u = v[t];
        u.x = fmaf(u.x, sc, sh_);
        u.y = fmaf(u.y, sc, sh_);
        u.z = fmaf(u.z, sc, sh_);
        u.w = fmaf(u.w, sc, sh_);
        p[tid + t*256] = u;
    }
}

// ---------------- pool (float4, unrolled) ----------------
__global__ __launch_bounds__(256)
void pool_k(const float* __restrict__ xf, float* __restrict__ g)
{
    int bc = blockIdx.x;
    const float4* p = (const float4*)(xf + (size_t)bc * NPIX);
    int tid = threadIdx.x;
    float mx = -1e30f, sm = 0.f;
    #pragma unroll
    for (int t = 0; t < 16; t++) {
        float4 v = p[tid + t*256];
        mx = fmaxf(mx, fmaxf(fmaxf(v.x, v.y), fmaxf(v.z, v.w)));
        sm += (v.x + v.y) + (v.z + v.w);
    }
    __shared__ float smx[256], ssm[256];
    smx[tid] = mx; ssm[tid] = sm;
    __syncthreads();
    for (int st = 128; st; st >>= 1) {
        if (tid < st) { smx[tid] = fmaxf(smx[tid], smx[tid+st]); ssm[tid] += ssm[tid+st]; }
        __syncthreads();
    }
    if (tid == 0) g[bc] = smx[0] + ssm[0] * (1.f/NPIX);
}

// ---------------- gating ----------------
__global__ void gate_k(const float* __restrict__ g,
                       const float* __restrict__ gw0, const float* __restrict__ gb0,
                       const float* __restrict__ gw1, const float* __restrict__ gb1,
                       float* __restrict__ cof_out, int* __restrict__ sel,
                       float* __restrict__ cofsel)
{
    int b = threadIdx.x;
    if (b >= Bsz) return;
    float lg[4], noi[4];
    for (int e = 0; e < 4; e++) {
        float a0 = gb0[e], a1 = gb1[e];
        for (int c = 0; c < 64; c++) {
            float gv = g[b*64 + c];
            a0 += gw0[e*64 + c] * gv;
            a1 += gw1[e*64 + c] * gv;
        }
        lg[e] = a1 > 0.f ? a1 : LEAKv * a1;
        noi[e] = fmaxf(a0, 0.f) + log1pf(expf(-fabsf(a0)));
    }
    float m = 0.25f * (noi[0] + noi[1] + noi[2] + noi[3]);
    float var = 0.f;
    for (int e = 0; e < 4; e++) { float dd = noi[e] - m; var += dd*dd; }
    float sd = sqrtf(var / 3.f);
    float sc[4];
    for (int e = 0; e < 4; e++) sc[e] = lg[e] + (noi[e] - m) / sd;
    int i0 = 0;
    for (int e = 1; e < 4; e++) if (sc[e] > sc[i0]) i0 = e;
    int i1 = -1;
    for (int e = 0; e < 4; e++) {
        if (e == i0) continue;
        if (i1 < 0 || sc[e] > sc[i1]) i1 = e;
    }
    float mm = fmaxf(lg[i0], lg[i1]);
    float e0 = expf(lg[i0] - mm), e1 = expf(lg[i1] - mm);
    float c0 = e0 / (e0 + e1), c1 = e1 / (e0 + e1);
    if (cof_out) {
        for (int e = 0; e < 4; e++) cof_out[b*4 + e] = 0.f;
        cof_out[b*4 + i0] = c0;
        cof_out[b*4 + i1] = c1;
    }
    sel[b*2 + 0] = i0; sel[b*2 + 1] = i1;
    cofsel[b*2 + 0] = c0; cofsel[b*2 + 1] = c1;
}

// ---------------- launch ----------------
extern "C" void kernel_launch(void* const* d_in, const int* in_sizes, int n_in,
                              void* d_out, int out_size)
{
    const float* x       = (const float*)d_in[0];
    const float* winv    = (const float*)d_in[1];
    const float* blk_w1  = (const float*)d_in[2];
    const float* blk_b1  = (const float*)d_in[3];
    const float* blk_nw  = (const float*)d_in[4];
    const float* blk_nb  = (const float*)d_in[5];
    const float* blk_w2  = (const float*)d_in[6];
    const float* blk_b2  = (const float*)d_in[7];
    const float* fuse_w  = (const float*)d_in[8];
    const float* fuse_b  = (const float*)d_in[9];
    const float* gw0     = (const float*)d_in[10];
    const float* gb0     = (const float*)d_in[11];
    const float* gw1     = (const float*)d_in[12];
    const float* gb1     = (const float*)d_in[13];
    const float* ew1     = (const float*)d_in[14];
    const float* eb1     = (const float*)d_in[15];
    const float* ew2     = (const float*)d_in[16];
    const float* eb2     = (const float*)d_in[17];
    float* out = (float*)d_out;
    float* cof_out = ((size_t)out_size >= BS + Bsz*4) ? out + BS : nullptr;

    float *x1, *x2, *y1, *y2, *rb, *sb, *xf, *hb, *gv, *cofsel; int* sel; uint2* wpack;
    void* p;
    cudaGetSymbolAddress(&p, g_x1);  x1 = (float*)p;
    cudaGetSymbolAddress(&p, g_x2);  x2 = (float*)p;
    cudaGetSymbolAddress(&p, g_y1);  y1 = (float*)p;
    cudaGetSymbolAddress(&p, g_y2);  y2 = (float*)p;
    cudaGetSymbolAddress(&p, g_rb);  rb = (float*)p;
    cudaGetSymbolAddress(&p, g_sb);  sb = (float*)p;
    cudaGetSymbolAddress(&p, g_xf);  xf = (float*)p;
    cudaGetSymbolAddress(&p, g_hb);  hb = (float*)p;
    cudaGetSymbolAddress(&p, g_gv);  gv = (float*)p;
    cudaGetSymbolAddress(&p, g_sel); sel = (int*)p;
    cudaGetSymbolAddress(&p, g_cofsel); cofsel = (float*)p;
    cudaGetSymbolAddress(&p, g_wpack);  wpack = (uint2*)p;

    dim3 cgrid(HWd/CTW, HWd/CTH, Bsz);
    dim3 cgrid4(HWd/CTW, HWd/CTH, Bsz*2);
    dim3 wgrid(NPIX/128, 2, Bsz);
    dim3 fgrid(NPIX/128, 1, Bsz);

    pack_all<<<(14*WSET+255)/256, 256>>>(blk_w1, blk_w2, ew1, ew2, wpack);

    gemm1x1_mma<128><<<wgrid, 256>>>(x, nullptr, winv, nullptr, x1, x2);

    conv3x3_mma<0><<<cgrid, 256>>>(x2, wpack + 0*WSET, blk_b1 + 0*64, rb,
                                   nullptr, nullptr, nullptr, nullptr, nullptr, nullptr);
    inorm_k<<<Bsz*32, 256>>>(rb, blk_nw + 0*32, blk_nb + 0*32);
    conv3x3_mma<1><<<cgrid, 256>>>(rb, wpack + 3*WSET, blk_b2 + 0*64, y1,
                                   x2, x1, nullptr, nullptr, nullptr, nullptr);

    conv3x3_mma<0><<<cgrid, 256>>>(y1, wpack + 2*WSET, blk_b1 + 2*64, rb,
                                   nullptr, nullptr, nullptr, nullptr, nullptr, nullptr);
    inorm_k<<<Bsz*32, 256>>>(rb, blk_nw + 2*32, blk_nb + 2*32);
    conv3x3_mma<2><<<cgrid, 256>>>(rb, wpack + 5*WSET, blk_b2 + 2*64, sb,
                                   y1, nullptr, nullptr, nullptr, nullptr, nullptr);

    conv3x3_mma<0><<<cgrid, 256>>>(y1, wpack + 1*WSET, blk_b1 + 1*64, rb,
                                   nullptr, nullptr, nullptr, nullptr, nullptr, nullptr);
    inorm_k<<<Bsz*32, 256>>>(rb, blk_nw + 1*32, blk_nb + 1*32);
    conv3x3_mma<3><<<cgrid, 256>>>(rb, wpack + 4*WSET, blk_b2 + 1*64, y2,
                                   y1, x2, sb, nullptr, nullptr, nullptr);

    gemm1x1_mma<128><<<fgrid, 256>>>(y1, y2, fuse_w, fuse_b, xf, nullptr);

    pool_k<<<Bsz*64, 256>>>(xf, gv);
    gate_k<<<1, 32>>>(gv, gw0, gb0, gw1, gb1, cof_out, sel, cofsel);

    conv3x3_mma<4><<<cgrid4, 256>>>(xf, wpack + 6*WSET, eb1, hb,
                                    nullptr, nullptr, nullptr, sel, cofsel, rb);
    conv3x3_mma<5><<<cgrid, 256>>>(hb, wpack + 10*WSET, eb2, out,
                                   xf, rb, nullptr, sel, cofsel, nullptr);
}